// round 2
// baseline (speedup 1.0000x reference)
#include <cuda_runtime.h>
#include <cuda_bf16.h>
#include <math.h>

#define SEQ   200
#define BATCH 32
#define EMB   300
#define HID   1000
#define GH    4000   // 4*HID
#define TAGS  9

// ---------------- scratch (module-load allocated, allowed) ----------------
__device__ float g_xg [SEQ * BATCH * GH];    // [T][B][4H]
__device__ float g_hs [SEQ * BATCH * HID];   // [T][B][H]
__device__ float g_c  [BATCH * HID];         // [B][H]
__device__ float g_tag[SEQ * BATCH * TAGS];  // [T][B][K] -> becomes emissions in-place

// ===========================================================================
// Kernel 1: xg[m][n] = dot(embed_w[x[m]], W_ih[n]) + b_ih[n] + b_hh[n]
// M=6400 (t*32+b), N=4000, K=300.  64x64 tile, BK=16, 256 threads, 4x4 micro.
// ===========================================================================
__global__ void xg_gemm_kernel(const int* __restrict__ x,
                               const float* __restrict__ embed_w,
                               const float* __restrict__ Wih,
                               const float* __restrict__ b_ih,
                               const float* __restrict__ b_hh)
{
    __shared__ __align__(16) float As[16][68];
    __shared__ __align__(16) float Bs[16][68];
    __shared__ int toks[64];

    const int tid = threadIdx.x;
    const int bm  = blockIdx.y * 64;
    const int bn  = blockIdx.x * 64;

    if (tid < 64) toks[tid] = x[bm + tid];
    __syncthreads();

    const int tx = tid & 15;       // 0..15 (n micro)
    const int ty = tid >> 4;       // 0..15 (m micro)

    // load mapping: each thread loads 4 consecutive k for one row
    const int lrow = tid >> 2;            // 0..63
    const int lk0  = (tid & 3) * 4;       // 0,4,8,12

    float acc[4][4];
#pragma unroll
    for (int i = 0; i < 4; i++)
#pragma unroll
        for (int j = 0; j < 4; j++) acc[i][j] = 0.f;

    const int ncol = bn + lrow;
    const float* wrow = Wih + (size_t)ncol * EMB;

    for (int k0 = 0; k0 < EMB; k0 += 16) {
        const float* erow = embed_w + (size_t)toks[lrow] * EMB;
#pragma unroll
        for (int i = 0; i < 4; i++) {
            int k = lk0 + i;
            As[k][lrow] = (k0 + k < EMB) ? erow[k0 + k] : 0.f;
            Bs[k][lrow] = (ncol < GH && k0 + k < EMB) ? wrow[k0 + k] : 0.f;
        }
        __syncthreads();
#pragma unroll
        for (int k = 0; k < 16; k++) {
            float4 a4 = *reinterpret_cast<const float4*>(&As[k][ty * 4]);
            float4 b4 = *reinterpret_cast<const float4*>(&Bs[k][tx * 4]);
            float ra[4] = {a4.x, a4.y, a4.z, a4.w};
            float rb[4] = {b4.x, b4.y, b4.z, b4.w};
#pragma unroll
            for (int i = 0; i < 4; i++)
#pragma unroll
                for (int j = 0; j < 4; j++) acc[i][j] += ra[i] * rb[j];
        }
        __syncthreads();
    }

#pragma unroll
    for (int i = 0; i < 4; i++) {
        int m = bm + ty * 4 + i;
#pragma unroll
        for (int j = 0; j < 4; j++) {
            int n = bn + tx * 4 + j;
            if (n < GH)
                g_xg[(size_t)m * GH + n] = acc[i][j] + b_ih[n] + b_hh[n];
        }
    }
}

// ===========================================================================
// Kernel 2: one LSTM timestep.
// grid = 125 blocks (8 h-cols each), 256 threads.
// thread bits: [ks(2) | bq(3) | jj(3)] ; thread owns 4 batches x 1 col x 4 gates,
// K split 4-way by ks (stride-4 interleave), reduced via smem.
// ===========================================================================
__global__ void lstm_step_kernel(const float* __restrict__ Whh, int t)
{
    const int tid = threadIdx.x;
    const int ks  = tid >> 6;        // 0..3
    const int bq  = (tid >> 3) & 7;  // 0..7  -> batches 4*bq..4*bq+3
    const int jj  = tid & 7;         // 0..7
    const int j0  = blockIdx.x * 8;

    const int KCP = 129;
    __shared__ float sh[2 * 32 * 129];   // [h | w], 33 KB
    float* sh_h = sh;
    float* sh_w = sh + 32 * KCP;

    float acc[4][4];
#pragma unroll
    for (int u = 0; u < 4; u++)
#pragma unroll
        for (int g = 0; g < 4; g++) acc[u][g] = 0.f;

    if (t > 0) {
        const float* hprev = g_hs + (size_t)(t - 1) * BATCH * HID;
        const int lr  = tid >> 3;   // 0..31 row to load
        const int lc0 = tid & 7;
        const int wg  = lr >> 3, wjj = lr & 7;
        const float* wrow = Whh + (size_t)(wg * HID + j0 + wjj) * HID;
        const float* hrow = hprev + (size_t)lr * HID;

        for (int k0 = 0; k0 < HID; k0 += 128) {
            const int KC = min(128, HID - k0);   // 128 x7, then 104
            for (int cc = lc0; cc < KC; cc += 8) {
                sh_h[lr * KCP + cc] = hrow[k0 + cc];
                sh_w[lr * KCP + cc] = wrow[k0 + cc];
            }
            __syncthreads();
            const int niter = KC >> 2;
            for (int i2 = 0; i2 < niter; i2++) {
                const int k = (i2 << 2) + ks;
                float hv0 = sh_h[(bq * 4 + 0) * KCP + k];
                float hv1 = sh_h[(bq * 4 + 1) * KCP + k];
                float hv2 = sh_h[(bq * 4 + 2) * KCP + k];
                float hv3 = sh_h[(bq * 4 + 3) * KCP + k];
#pragma unroll
                for (int g = 0; g < 4; g++) {
                    float wv = sh_w[(g * 8 + jj) * KCP + k];
                    acc[0][g] += hv0 * wv;
                    acc[1][g] += hv1 * wv;
                    acc[2][g] += hv2 * wv;
                    acc[3][g] += hv3 * wv;
                }
            }
            __syncthreads();
        }
    }

    // ks-reduction through smem: red[bq][jj][u][g][ks]
    float* red = sh;
#pragma unroll
    for (int u = 0; u < 4; u++)
#pragma unroll
        for (int g = 0; g < 4; g++)
            red[(((bq * 8 + jj) * 4 + u) * 4 + g) * 4 + ks] = acc[u][g];
    __syncthreads();

    if (ks == 0) {
        const float* xgt = g_xg + (size_t)t * BATCH * GH;
        const int j = j0 + jj;
#pragma unroll
        for (int u = 0; u < 4; u++) {
            const int b = bq * 4 + u;
            float gate[4];
#pragma unroll
            for (int g = 0; g < 4; g++) {
                const float* p = &red[(((bq * 8 + jj) * 4 + u) * 4 + g) * 4];
                gate[g] = p[0] + p[1] + p[2] + p[3] + xgt[b * GH + g * HID + j];
            }
            float iv = 1.f / (1.f + expf(-gate[0]));
            float fv = 1.f / (1.f + expf(-gate[1]));
            float gv = tanhf(gate[2]);
            float ov = 1.f / (1.f + expf(-gate[3]));
            float cold = (t == 0) ? 0.f : g_c[b * HID + j];
            float cn = fv * cold + iv * gv;
            float hn = ov * tanhf(cn);
            g_c[b * HID + j] = cn;
            g_hs[(size_t)t * BATCH * HID + b * HID + j] = hn;
        }
    }
}

// ===========================================================================
// Kernel 3: tag_space[t,b,k] = dot(hs[t,b], lin_w[k]) + lin_b[k]
// grid 6400 (=t*32+b), 288 threads (warp per k).
// ===========================================================================
__global__ void tag_kernel(const float* __restrict__ lin_w,
                           const float* __restrict__ lin_b)
{
    const int tb   = blockIdx.x;
    const int k    = threadIdx.x >> 5;   // 0..8
    const int lane = threadIdx.x & 31;
    const float* hrow = g_hs + (size_t)tb * HID;
    const float* wrow = lin_w + k * HID;
    float s = 0.f;
    for (int kk = lane; kk < HID; kk += 32) s += hrow[kk] * wrow[kk];
#pragma unroll
    for (int off = 16; off; off >>= 1) s += __shfl_down_sync(0xffffffffu, s, off);
    if (lane == 0) g_tag[tb * TAGS + k] = s + lin_b[k];
}

// ===========================================================================
// Kernel 4: log_softmax over the BATCH axis (axis=1), in place.
// grid 200 (t), 288 threads: warp = k, lane = b.
// ===========================================================================
__global__ void lsm_kernel()
{
    const int t = blockIdx.x;
    const int k = threadIdx.x >> 5;
    const int b = threadIdx.x & 31;
    float v = g_tag[(t * BATCH + b) * TAGS + k];
    float m = v;
#pragma unroll
    for (int off = 16; off; off >>= 1) m = fmaxf(m, __shfl_xor_sync(0xffffffffu, m, off));
    float e = expf(v - m);
    float s = e;
#pragma unroll
    for (int off = 16; off; off >>= 1) s += __shfl_xor_sync(0xffffffffu, s, off);
    g_tag[(t * BATCH + b) * TAGS + k] = v - m - logf(s);
}

// ===========================================================================
// Kernel 5: CRF forward + numerator + final sum. single block, 288 threads.
// ===========================================================================
__global__ void crf_kernel(const int* __restrict__ y,
                           const float* __restrict__ start_t,
                           const float* __restrict__ end_t,
                           const float* __restrict__ trans,
                           float* __restrict__ out)
{
    __shared__ float alpha[BATCH][TAGS];
    __shared__ float tr[TAGS][TAGS];
    __shared__ float st[TAGS], en[TAGS];
    __shared__ float numer[BATCH], logz[BATCH];

    const int tid = threadIdx.x;
    if (tid < 81) tr[tid / 9][tid % 9] = trans[tid];
    if (tid < 9) { st[tid] = start_t[tid]; en[tid] = end_t[tid]; }
    __syncthreads();

    const int b = tid / 9, k = tid % 9;
    alpha[b][k] = st[k] + g_tag[(0 * BATCH + b) * TAGS + k];
    __syncthreads();

    for (int t = 1; t < SEQ; t++) {
        float av[9];
#pragma unroll
        for (int kp = 0; kp < 9; kp++) av[kp] = alpha[b][kp] + tr[kp][k];
        float m = av[0];
#pragma unroll
        for (int kp = 1; kp < 9; kp++) m = fmaxf(m, av[kp]);
        float s = 0.f;
#pragma unroll
        for (int kp = 0; kp < 9; kp++) s += expf(av[kp] - m);
        float nxt = m + logf(s) + g_tag[(t * BATCH + b) * TAGS + k];
        __syncthreads();
        alpha[b][k] = nxt;
        __syncthreads();
    }

    if (k == 0) {
        float m = alpha[b][0] + en[0];
#pragma unroll
        for (int kp = 1; kp < 9; kp++) m = fmaxf(m, alpha[b][kp] + en[kp]);
        float s = 0.f;
#pragma unroll
        for (int kp = 0; kp < 9; kp++) s += expf(alpha[b][kp] + en[kp] - m);
        logz[b] = m + logf(s);

        int yprev = y[0 * BATCH + b];
        float num = st[yprev] + g_tag[(0 * BATCH + b) * TAGS + yprev];
        for (int t = 1; t < SEQ; t++) {
            int yt = y[t * BATCH + b];
            num += tr[yprev][yt] + g_tag[(t * BATCH + b) * TAGS + yt];
            yprev = yt;
        }
        num += en[yprev];
        numer[b] = num;
    }
    __syncthreads();

    if (tid == 0) {
        float s = 0.f;
        for (int bb = 0; bb < BATCH; bb++) s += numer[bb] - logz[bb];
        out[0] = s;
    }
}

// ===========================================================================
// launch
// ===========================================================================
extern "C" void kernel_launch(void* const* d_in, const int* in_sizes, int n_in,
                              void* d_out, int out_size)
{
    const int*   x       = (const int*)  d_in[0];
    const int*   y       = (const int*)  d_in[1];
    const float* embed_w = (const float*)d_in[2];
    const float* W_ih    = (const float*)d_in[3];
    const float* W_hh    = (const float*)d_in[4];
    const float* b_ih    = (const float*)d_in[5];
    const float* b_hh    = (const float*)d_in[6];
    const float* lin_w   = (const float*)d_in[7];
    const float* lin_b   = (const float*)d_in[8];
    const float* start_t = (const float*)d_in[9];
    const float* end_t   = (const float*)d_in[10];
    const float* trans   = (const float*)d_in[11];
    float* out = (float*)d_out;

    // 1) input-gate precompute GEMM
    xg_gemm_kernel<<<dim3(63, 100), 256>>>(x, embed_w, W_ih, b_ih, b_hh);

    // 2) sequential LSTM scan
    for (int t = 0; t < SEQ; t++)
        lstm_step_kernel<<<125, 256>>>(W_hh, t);

    // 3) tag space projection
    tag_kernel<<<SEQ * BATCH, 288>>>(lin_w, lin_b);

    // 4) log_softmax over batch axis
    lsm_kernel<<<SEQ, 288>>>();

    // 5) CRF forward + loss
    crf_kernel<<<1, 288>>>(y, start_t, end_t, trans, out);
}

// round 3
// speedup vs baseline: 1.5244x; 1.5244x over previous
#include <cuda_runtime.h>
#include <cuda_bf16.h>
#include <math.h>

#define SEQ   200
#define BATCH 32
#define EMB   300
#define HID   1000
#define GH    4000   // 4*HID
#define TAGS  9

#define NBLK  125    // persistent blocks, 8 j-cols each
#define JB    8
#define CH    200    // h k-chunk (5 chunks of 200 = 1000)
#define NCH   5

// ---------------- scratch ----------------
__device__ float g_xg [SEQ * GH * BATCH];    // [t][n][b]   n = g*HID + j
__device__ float g_hs [SEQ * HID * BATCH];   // [t][j][b]
__device__ float g_tag[SEQ * BATCH * TAGS];  // [t][b][k]
__device__ unsigned g_cnt = 0;
__device__ unsigned g_gen = 0;

// ===========================================================================
// Kernel 1: xg[t][n][b] = dot(embed_w[x[t,b]], W_ih[n]) + b_ih[n] + b_hh[n]
// M=6400 (t*32+b), N=4000, K=300.  64x64 tile, BK=16, 256 threads, 4x4 micro.
// ===========================================================================
__global__ void xg_gemm_kernel(const int* __restrict__ x,
                               const float* __restrict__ embed_w,
                               const float* __restrict__ Wih,
                               const float* __restrict__ b_ih,
                               const float* __restrict__ b_hh)
{
    __shared__ __align__(16) float As[16][68];
    __shared__ __align__(16) float Bs[16][68];
    __shared__ int toks[64];

    const int tid = threadIdx.x;
    const int bm  = blockIdx.y * 64;
    const int bn  = blockIdx.x * 64;

    if (tid < 64) toks[tid] = x[bm + tid];
    __syncthreads();

    const int tx = tid & 15;
    const int ty = tid >> 4;
    const int lrow = tid >> 2;
    const int lk0  = (tid & 3) * 4;

    float acc[4][4];
#pragma unroll
    for (int i = 0; i < 4; i++)
#pragma unroll
        for (int j = 0; j < 4; j++) acc[i][j] = 0.f;

    const int ncol = bn + lrow;
    const float* wrow = Wih + (size_t)ncol * EMB;

    for (int k0 = 0; k0 < EMB; k0 += 16) {
        const float* erow = embed_w + (size_t)toks[lrow] * EMB;
#pragma unroll
        for (int i = 0; i < 4; i++) {
            int k = lk0 + i;
            As[k][lrow] = (k0 + k < EMB) ? erow[k0 + k] : 0.f;
            Bs[k][lrow] = (ncol < GH && k0 + k < EMB) ? wrow[k0 + k] : 0.f;
        }
        __syncthreads();
#pragma unroll
        for (int k = 0; k < 16; k++) {
            float4 a4 = *reinterpret_cast<const float4*>(&As[k][ty * 4]);
            float4 b4 = *reinterpret_cast<const float4*>(&Bs[k][tx * 4]);
            float ra[4] = {a4.x, a4.y, a4.z, a4.w};
            float rb[4] = {b4.x, b4.y, b4.z, b4.w};
#pragma unroll
            for (int i = 0; i < 4; i++)
#pragma unroll
                for (int j = 0; j < 4; j++) acc[i][j] += ra[i] * rb[j];
        }
        __syncthreads();
    }

#pragma unroll
    for (int i = 0; i < 4; i++) {
        int m = bm + ty * 4 + i;
        int t = m >> 5, b = m & 31;
#pragma unroll
        for (int j = 0; j < 4; j++) {
            int n = bn + tx * 4 + j;
            if (n < GH)
                g_xg[((size_t)t * GH + n) * BATCH + b] = acc[i][j] + b_ih[n] + b_hh[n];
        }
    }
}

// ===========================================================================
// Kernel 2: persistent LSTM scan. 125 blocks x 256 threads, 1 block/SM.
// W_hh slice cached in smem once; grid barrier between steps; c in registers.
// thread bits (compute role): tid = ks(3)<<5 | bg(2)<<3 | jj(3)
//   -> warp = ks (k-slice), lanes = (bg,jj): conflict-free smem broadcasts.
// combine role: tid = cjj(3)<<5 | b(5) -> one (b,j) output per thread.
// ===========================================================================
__global__ void __launch_bounds__(256, 1)
lstm_persist_kernel(const float* __restrict__ Whh)
{
    extern __shared__ float sm[];
    float* w_sm = sm;                       // [1000][32]  w_sm[k*32 + jj*4 + g]
    float* h_sm = sm + 32 * HID;            // [CH][32]
    float* red  = sm + 32 * HID + CH * 32;  // [256][33]

    const int tid = threadIdx.x;
    const int j0  = blockIdx.x * JB;

    const int ks = tid >> 5;
    const int bg = (tid >> 3) & 3;
    const int jj = tid & 7;

    const int cb  = tid & 31;   // combine: batch
    const int cjj = tid >> 5;   // combine: j within block

    // ---- load W slice once: lane = (jw,g), warps split k ----
    {
        const int lane = tid & 31;
        const int w    = tid >> 5;
        const int g    = lane & 3;
        const int jw   = lane >> 2;
        const float* src = Whh + ((size_t)(g * HID + j0 + jw)) * HID;
        for (int k = w * 125; k < (w + 1) * 125; k++)
            w_sm[k * 32 + lane] = src[k];           // conflict-free STS
    }
    float c_reg = 0.f;
    __syncthreads();

    for (int t = 0; t < SEQ; t++) {
        float acc[8][4];
#pragma unroll
        for (int u = 0; u < 8; u++)
#pragma unroll
            for (int g = 0; g < 4; g++) acc[u][g] = 0.f;

        if (t > 0) {
            const float* hprev = g_hs + (size_t)(t - 1) * HID * BATCH;
            for (int ch = 0; ch < NCH; ch++) {
                __syncthreads();
                const float4* src = (const float4*)(hprev + (size_t)ch * CH * 32);
                float4* dst = (float4*)h_sm;
                for (int i = tid; i < CH * 32 / 4; i += 256) dst[i] = src[i];
                __syncthreads();
#pragma unroll 5
                for (int i = 0; i < 25; i++) {
                    const int kl = ks + 8 * i;
                    float4 w4 = *(const float4*)&w_sm[(ch * CH + kl) * 32 + jj * 4];
                    float4 ha = *(const float4*)&h_sm[kl * 32 + bg * 8];
                    float4 hb = *(const float4*)&h_sm[kl * 32 + bg * 8 + 4];
                    float hv[8] = {ha.x, ha.y, ha.z, ha.w, hb.x, hb.y, hb.z, hb.w};
                    float wv[4] = {w4.x, w4.y, w4.z, w4.w};
#pragma unroll
                    for (int u = 0; u < 8; u++)
#pragma unroll
                        for (int g = 0; g < 4; g++) acc[u][g] += hv[u] * wv[g];
                }
            }
        }

        // ---- stage partials: per-thread contiguous, stride-33 (conflict-free) ----
        __syncthreads();
        {
            float* myred = red + tid * 33;
#pragma unroll
            for (int u = 0; u < 8; u++)
#pragma unroll
                for (int g = 0; g < 4; g++) myred[u * 4 + g] = acc[u][g];
        }
        __syncthreads();

        // ---- combine: thread owns (b=cb, j=j0+cjj) ----
        {
            const float* xgt = g_xg + (size_t)t * GH * BATCH;
            const int b = cb, j = j0 + cjj;
            const int bgc = b >> 3, uc = b & 7;
            float gate[4];
#pragma unroll
            for (int g = 0; g < 4; g++) {
                float s = 0.f;
#pragma unroll
                for (int k2 = 0; k2 < 8; k2++)
                    s += red[(k2 * 32 + bgc * 8 + cjj) * 33 + uc * 4 + g];
                gate[g] = s + xgt[((size_t)(g * HID + j)) * BATCH + b];
            }
            float iv = 1.f / (1.f + expf(-gate[0]));
            float fv = 1.f / (1.f + expf(-gate[1]));
            float gv = tanhf(gate[2]);
            float ov = 1.f / (1.f + expf(-gate[3]));
            c_reg = fv * c_reg + iv * gv;
            float hn = ov * tanhf(c_reg);
            g_hs[((size_t)t * HID + j) * BATCH + b] = hn;
        }

        // ---- grid barrier (sense-reversing) ----
        __threadfence();          // publish h stores (all threads)
        __syncthreads();
        if (tid == 0) {
            unsigned my = atomicAdd(&g_gen, 0u);
            if (atomicAdd(&g_cnt, 1u) == NBLK - 1) {
                atomicExch(&g_cnt, 0u);
                __threadfence();
                atomicAdd(&g_gen, 1u);
            } else {
                while (*(volatile unsigned*)&g_gen == my) { }
            }
            __threadfence();
        }
        __syncthreads();
    }
}

// ===========================================================================
// Kernel 3: tag[t][b][k] = dot over j of hs[t][j][b] * lin_w[k][j] + lin_b[k]
// grid SEQ, 288 threads = k(9) x b(32). Coalesced over b, lin_w broadcast.
// ===========================================================================
__global__ void tag_kernel(const float* __restrict__ lin_w,
                           const float* __restrict__ lin_b)
{
    const int t = blockIdx.x;
    const int k = threadIdx.x >> 5;
    const int b = threadIdx.x & 31;
    const float* h = g_hs + (size_t)t * HID * BATCH;
    const float* w = lin_w + k * HID;
    float s = 0.f;
#pragma unroll 4
    for (int j = 0; j < HID; j++) s += h[j * BATCH + b] * w[j];
    g_tag[(t * BATCH + b) * TAGS + k] = s + lin_b[k];
}

// ===========================================================================
// Kernel 4: log_softmax over BATCH axis (axis=1), in place.
// ===========================================================================
__global__ void lsm_kernel()
{
    const int t = blockIdx.x;
    const int k = threadIdx.x >> 5;
    const int b = threadIdx.x & 31;
    float v = g_tag[(t * BATCH + b) * TAGS + k];
    float m = v;
#pragma unroll
    for (int off = 16; off; off >>= 1) m = fmaxf(m, __shfl_xor_sync(0xffffffffu, m, off));
    float e = expf(v - m);
    float s = e;
#pragma unroll
    for (int off = 16; off; off >>= 1) s += __shfl_xor_sync(0xffffffffu, s, off);
    g_tag[(t * BATCH + b) * TAGS + k] = v - m - logf(s);
}

// ===========================================================================
// Kernel 5: CRF forward + numerator + final sum. single block.
// ===========================================================================
__global__ void crf_kernel(const int* __restrict__ y,
                           const float* __restrict__ start_t,
                           const float* __restrict__ end_t,
                           const float* __restrict__ trans,
                           float* __restrict__ out)
{
    __shared__ float alpha[BATCH][TAGS];
    __shared__ float tr[TAGS][TAGS];
    __shared__ float st[TAGS], en[TAGS];
    __shared__ float numer[BATCH], logz[BATCH];

    const int tid = threadIdx.x;
    if (tid < 81) tr[tid / 9][tid % 9] = trans[tid];
    if (tid < 9) { st[tid] = start_t[tid]; en[tid] = end_t[tid]; }
    __syncthreads();

    const int b = tid / 9, k = tid % 9;
    alpha[b][k] = st[k] + g_tag[(0 * BATCH + b) * TAGS + k];
    __syncthreads();

    for (int t = 1; t < SEQ; t++) {
        float av[9];
#pragma unroll
        for (int kp = 0; kp < 9; kp++) av[kp] = alpha[b][kp] + tr[kp][k];
        float m = av[0];
#pragma unroll
        for (int kp = 1; kp < 9; kp++) m = fmaxf(m, av[kp]);
        float s = 0.f;
#pragma unroll
        for (int kp = 0; kp < 9; kp++) s += expf(av[kp] - m);
        float nxt = m + logf(s) + g_tag[(t * BATCH + b) * TAGS + k];
        __syncthreads();
        alpha[b][k] = nxt;
        __syncthreads();
    }

    if (k == 0) {
        float m = alpha[b][0] + en[0];
#pragma unroll
        for (int kp = 1; kp < 9; kp++) m = fmaxf(m, alpha[b][kp] + en[kp]);
        float s = 0.f;
#pragma unroll
        for (int kp = 0; kp < 9; kp++) s += expf(alpha[b][kp] + en[kp] - m);
        logz[b] = m + logf(s);

        int yprev = y[0 * BATCH + b];
        float num = st[yprev] + g_tag[(0 * BATCH + b) * TAGS + yprev];
        for (int t = 1; t < SEQ; t++) {
            int yt = y[t * BATCH + b];
            num += tr[yprev][yt] + g_tag[(t * BATCH + b) * TAGS + yt];
            yprev = yt;
        }
        num += en[yprev];
        numer[b] = num;
    }
    __syncthreads();

    if (tid == 0) {
        float s = 0.f;
        for (int bb = 0; bb < BATCH; bb++) s += numer[bb] - logz[bb];
        out[0] = s;
    }
}

// ===========================================================================
// launch
// ===========================================================================
extern "C" void kernel_launch(void* const* d_in, const int* in_sizes, int n_in,
                              void* d_out, int out_size)
{
    const int*   x       = (const int*)  d_in[0];
    const int*   y       = (const int*)  d_in[1];
    const float* embed_w = (const float*)d_in[2];
    const float* W_ih    = (const float*)d_in[3];
    const float* W_hh    = (const float*)d_in[4];
    const float* b_ih    = (const float*)d_in[5];
    const float* b_hh    = (const float*)d_in[6];
    const float* lin_w   = (const float*)d_in[7];
    const float* lin_b   = (const float*)d_in[8];
    const float* start_t = (const float*)d_in[9];
    const float* end_t   = (const float*)d_in[10];
    const float* trans   = (const float*)d_in[11];
    float* out = (float*)d_out;

    const int smem_bytes = (32 * HID + CH * 32 + 256 * 33) * sizeof(float); // 187392
    cudaFuncSetAttribute(lstm_persist_kernel,
                         cudaFuncAttributeMaxDynamicSharedMemorySize, smem_bytes);

    xg_gemm_kernel<<<dim3(63, 100), 256>>>(x, embed_w, W_ih, b_ih, b_hh);

    lstm_persist_kernel<<<NBLK, 256, smem_bytes>>>(W_hh);

    tag_kernel<<<SEQ, 288>>>(lin_w, lin_b);
    lsm_kernel<<<SEQ, 288>>>();
    crf_kernel<<<1, 288>>>(y, start_t, end_t, trans, out);
}

// round 4
// speedup vs baseline: 1.5291x; 1.0031x over previous
#include <cuda_runtime.h>
#include <cuda_bf16.h>
#include <math.h>

#define SEQ   200
#define BATCH 32
#define EMB   300
#define HID   1000
#define GH    4000   // 4*HID
#define TAGS  9

#define NBLK  125    // persistent blocks, 8 j-cols each
#define JB    8
#define CH    200    // h k-chunk (5 chunks of 200 = 1000)
#define NCH   5

// ---------------- scratch ----------------
__device__ float g_xg [SEQ * GH * BATCH];    // [t][n][b]   n = g*HID + j
__device__ float g_hs [SEQ * HID * BATCH];   // [t][j][b]
__device__ float g_tag[SEQ * BATCH * TAGS];  // [t][b][k]
__device__ unsigned g_cnt = 0;
__device__ unsigned g_gen = 0;

// ===========================================================================
// Kernel 1: xg[t][n][b] = dot(embed_w[x[t,b]], W_ih[n]) + b_ih[n] + b_hh[n]
// M=6400 (t*32+b), N=4000, K=300.  64x64 tile, BK=16, 256 threads, 4x4 micro.
// ===========================================================================
__global__ void xg_gemm_kernel(const int* __restrict__ x,
                               const float* __restrict__ embed_w,
                               const float* __restrict__ Wih,
                               const float* __restrict__ b_ih,
                               const float* __restrict__ b_hh)
{
    __shared__ __align__(16) float As[16][68];
    __shared__ __align__(16) float Bs[16][68];
    __shared__ int toks[64];

    const int tid = threadIdx.x;
    const int bm  = blockIdx.y * 64;
    const int bn  = blockIdx.x * 64;

    if (tid < 64) toks[tid] = x[bm + tid];
    __syncthreads();

    const int tx = tid & 15;
    const int ty = tid >> 4;
    const int lrow = tid >> 2;
    const int lk0  = (tid & 3) * 4;

    float acc[4][4];
#pragma unroll
    for (int i = 0; i < 4; i++)
#pragma unroll
        for (int j = 0; j < 4; j++) acc[i][j] = 0.f;

    const int ncol = bn + lrow;
    const float* wrow = Wih + (size_t)ncol * EMB;

    for (int k0 = 0; k0 < EMB; k0 += 16) {
        const float* erow = embed_w + (size_t)toks[lrow] * EMB;
#pragma unroll
        for (int i = 0; i < 4; i++) {
            int k = lk0 + i;
            As[k][lrow] = (k0 + k < EMB) ? erow[k0 + k] : 0.f;
            Bs[k][lrow] = (ncol < GH && k0 + k < EMB) ? wrow[k0 + k] : 0.f;
        }
        __syncthreads();
#pragma unroll
        for (int k = 0; k < 16; k++) {
            float4 a4 = *reinterpret_cast<const float4*>(&As[k][ty * 4]);
            float4 b4 = *reinterpret_cast<const float4*>(&Bs[k][tx * 4]);
            float ra[4] = {a4.x, a4.y, a4.z, a4.w};
            float rb[4] = {b4.x, b4.y, b4.z, b4.w};
#pragma unroll
            for (int i = 0; i < 4; i++)
#pragma unroll
                for (int j = 0; j < 4; j++) acc[i][j] += ra[i] * rb[j];
        }
        __syncthreads();
    }

#pragma unroll
    for (int i = 0; i < 4; i++) {
        int m = bm + ty * 4 + i;
        int t = m >> 5, b = m & 31;
#pragma unroll
        for (int j = 0; j < 4; j++) {
            int n = bn + tx * 4 + j;
            if (n < GH)
                g_xg[((size_t)t * GH + n) * BATCH + b] = acc[i][j] + b_ih[n] + b_hh[n];
        }
    }
}

// ===========================================================================
// Kernel 2: persistent LSTM scan. 125 blocks x 256 threads, 1 block/SM.
// W_hh slice cached in smem once; grid barrier between steps; c in registers.
// thread bits (compute role): tid = ks(3)<<5 | bg(2)<<3 | jj(3)
//   -> warp = ks (k-slice), lanes = (bg,jj): conflict-free smem broadcasts.
// combine role: tid = cjj(3)<<5 | b(5) -> one (b,j) output per thread.
// ===========================================================================
__global__ void __launch_bounds__(256, 1)
lstm_persist_kernel(const float* __restrict__ Whh)
{
    extern __shared__ float sm[];
    float* w_sm = sm;                       // [1000][32]  w_sm[k*32 + jj*4 + g]
    float* h_sm = sm + 32 * HID;            // [CH][32]
    float* red  = sm + 32 * HID + CH * 32;  // [256][33]

    const int tid = threadIdx.x;
    const int j0  = blockIdx.x * JB;

    const int ks = tid >> 5;
    const int bg = (tid >> 3) & 3;
    const int jj = tid & 7;

    const int cb  = tid & 31;   // combine: batch
    const int cjj = tid >> 5;   // combine: j within block

    // ---- load W slice once: lane = (jw,g), warps split k ----
    {
        const int lane = tid & 31;
        const int w    = tid >> 5;
        const int g    = lane & 3;
        const int jw   = lane >> 2;
        const float* src = Whh + ((size_t)(g * HID + j0 + jw)) * HID;
        for (int k = w * 125; k < (w + 1) * 125; k++)
            w_sm[k * 32 + lane] = src[k];           // conflict-free STS
    }
    float c_reg = 0.f;
    __syncthreads();

    for (int t = 0; t < SEQ; t++) {
        float acc[8][4];
#pragma unroll
        for (int u = 0; u < 8; u++)
#pragma unroll
            for (int g = 0; g < 4; g++) acc[u][g] = 0.f;

        if (t > 0) {
            const float* hprev = g_hs + (size_t)(t - 1) * HID * BATCH;
            for (int ch = 0; ch < NCH; ch++) {
                __syncthreads();
                const float4* src = (const float4*)(hprev + (size_t)ch * CH * 32);
                float4* dst = (float4*)h_sm;
                for (int i = tid; i < CH * 32 / 4; i += 256) dst[i] = src[i];
                __syncthreads();
#pragma unroll 5
                for (int i = 0; i < 25; i++) {
                    const int kl = ks + 8 * i;
                    float4 w4 = *(const float4*)&w_sm[(ch * CH + kl) * 32 + jj * 4];
                    float4 ha = *(const float4*)&h_sm[kl * 32 + bg * 8];
                    float4 hb = *(const float4*)&h_sm[kl * 32 + bg * 8 + 4];
                    float hv[8] = {ha.x, ha.y, ha.z, ha.w, hb.x, hb.y, hb.z, hb.w};
                    float wv[4] = {w4.x, w4.y, w4.z, w4.w};
#pragma unroll
                    for (int u = 0; u < 8; u++)
#pragma unroll
                        for (int g = 0; g < 4; g++) acc[u][g] += hv[u] * wv[g];
                }
            }
        }

        // ---- stage partials: per-thread contiguous, stride-33 (conflict-free) ----
        __syncthreads();
        {
            float* myred = red + tid * 33;
#pragma unroll
            for (int u = 0; u < 8; u++)
#pragma unroll
                for (int g = 0; g < 4; g++) myred[u * 4 + g] = acc[u][g];
        }
        __syncthreads();

        // ---- combine: thread owns (b=cb, j=j0+cjj) ----
        {
            const float* xgt = g_xg + (size_t)t * GH * BATCH;
            const int b = cb, j = j0 + cjj;
            const int bgc = b >> 3, uc = b & 7;
            float gate[4];
#pragma unroll
            for (int g = 0; g < 4; g++) {
                float s = 0.f;
#pragma unroll
                for (int k2 = 0; k2 < 8; k2++)
                    s += red[(k2 * 32 + bgc * 8 + cjj) * 33 + uc * 4 + g];
                gate[g] = s + xgt[((size_t)(g * HID + j)) * BATCH + b];
            }
            float iv = 1.f / (1.f + expf(-gate[0]));
            float fv = 1.f / (1.f + expf(-gate[1]));
            float gv = tanhf(gate[2]);
            float ov = 1.f / (1.f + expf(-gate[3]));
            c_reg = fv * c_reg + iv * gv;
            float hn = ov * tanhf(c_reg);
            g_hs[((size_t)t * HID + j) * BATCH + b] = hn;
        }

        // ---- grid barrier (sense-reversing) ----
        __threadfence();          // publish h stores (all threads)
        __syncthreads();
        if (tid == 0) {
            unsigned my = atomicAdd(&g_gen, 0u);
            if (atomicAdd(&g_cnt, 1u) == NBLK - 1) {
                atomicExch(&g_cnt, 0u);
                __threadfence();
                atomicAdd(&g_gen, 1u);
            } else {
                while (*(volatile unsigned*)&g_gen == my) { }
            }
            __threadfence();
        }
        __syncthreads();
    }
}

// ===========================================================================
// Kernel 3: tag[t][b][k] = dot over j of hs[t][j][b] * lin_w[k][j] + lin_b[k]
// grid SEQ, 288 threads = k(9) x b(32). Coalesced over b, lin_w broadcast.
// ===========================================================================
__global__ void tag_kernel(const float* __restrict__ lin_w,
                           const float* __restrict__ lin_b)
{
    const int t = blockIdx.x;
    const int k = threadIdx.x >> 5;
    const int b = threadIdx.x & 31;
    const float* h = g_hs + (size_t)t * HID * BATCH;
    const float* w = lin_w + k * HID;
    float s = 0.f;
#pragma unroll 4
    for (int j = 0; j < HID; j++) s += h[j * BATCH + b] * w[j];
    g_tag[(t * BATCH + b) * TAGS + k] = s + lin_b[k];
}

// ===========================================================================
// Kernel 4: log_softmax over BATCH axis (axis=1), in place.
// ===========================================================================
__global__ void lsm_kernel()
{
    const int t = blockIdx.x;
    const int k = threadIdx.x >> 5;
    const int b = threadIdx.x & 31;
    float v = g_tag[(t * BATCH + b) * TAGS + k];
    float m = v;
#pragma unroll
    for (int off = 16; off; off >>= 1) m = fmaxf(m, __shfl_xor_sync(0xffffffffu, m, off));
    float e = expf(v - m);
    float s = e;
#pragma unroll
    for (int off = 16; off; off >>= 1) s += __shfl_xor_sync(0xffffffffu, s, off);
    g_tag[(t * BATCH + b) * TAGS + k] = v - m - logf(s);
}

// ===========================================================================
// Kernel 5: CRF forward + numerator + final sum. single block.
// ===========================================================================
__global__ void crf_kernel(const int* __restrict__ y,
                           const float* __restrict__ start_t,
                           const float* __restrict__ end_t,
                           const float* __restrict__ trans,
                           float* __restrict__ out)
{
    __shared__ float alpha[BATCH][TAGS];
    __shared__ float tr[TAGS][TAGS];
    __shared__ float st[TAGS], en[TAGS];
    __shared__ float numer[BATCH], logz[BATCH];

    const int tid = threadIdx.x;
    if (tid < 81) tr[tid / 9][tid % 9] = trans[tid];
    if (tid < 9) { st[tid] = start_t[tid]; en[tid] = end_t[tid]; }
    __syncthreads();

    const int b = tid / 9, k = tid % 9;
    alpha[b][k] = st[k] + g_tag[(0 * BATCH + b) * TAGS + k];
    __syncthreads();

    for (int t = 1; t < SEQ; t++) {
        float av[9];
#pragma unroll
        for (int kp = 0; kp < 9; kp++) av[kp] = alpha[b][kp] + tr[kp][k];
        float m = av[0];
#pragma unroll
        for (int kp = 1; kp < 9; kp++) m = fmaxf(m, av[kp]);
        float s = 0.f;
#pragma unroll
        for (int kp = 0; kp < 9; kp++) s += expf(av[kp] - m);
        float nxt = m + logf(s) + g_tag[(t * BATCH + b) * TAGS + k];
        __syncthreads();
        alpha[b][k] = nxt;
        __syncthreads();
    }

    if (k == 0) {
        float m = alpha[b][0] + en[0];
#pragma unroll
        for (int kp = 1; kp < 9; kp++) m = fmaxf(m, alpha[b][kp] + en[kp]);
        float s = 0.f;
#pragma unroll
        for (int kp = 0; kp < 9; kp++) s += expf(alpha[b][kp] + en[kp] - m);
        logz[b] = m + logf(s);

        int yprev = y[0 * BATCH + b];
        float num = st[yprev] + g_tag[(0 * BATCH + b) * TAGS + yprev];
        for (int t = 1; t < SEQ; t++) {
            int yt = y[t * BATCH + b];
            num += tr[yprev][yt] + g_tag[(t * BATCH + b) * TAGS + yt];
            yprev = yt;
        }
        num += en[yprev];
        numer[b] = num;
    }
    __syncthreads();

    if (tid == 0) {
        float s = 0.f;
        for (int bb = 0; bb < BATCH; bb++) s += numer[bb] - logz[bb];
        out[0] = s;
    }
}

// ===========================================================================
// launch
// ===========================================================================
extern "C" void kernel_launch(void* const* d_in, const int* in_sizes, int n_in,
                              void* d_out, int out_size)
{
    const int*   x       = (const int*)  d_in[0];
    const int*   y       = (const int*)  d_in[1];
    const float* embed_w = (const float*)d_in[2];
    const float* W_ih    = (const float*)d_in[3];
    const float* W_hh    = (const float*)d_in[4];
    const float* b_ih    = (const float*)d_in[5];
    const float* b_hh    = (const float*)d_in[6];
    const float* lin_w   = (const float*)d_in[7];
    const float* lin_b   = (const float*)d_in[8];
    const float* start_t = (const float*)d_in[9];
    const float* end_t   = (const float*)d_in[10];
    const float* trans   = (const float*)d_in[11];
    float* out = (float*)d_out;

    const int smem_bytes = (32 * HID + CH * 32 + 256 * 33) * sizeof(float); // 187392
    cudaFuncSetAttribute(lstm_persist_kernel,
                         cudaFuncAttributeMaxDynamicSharedMemorySize, smem_bytes);

    xg_gemm_kernel<<<dim3(63, 100), 256>>>(x, embed_w, W_ih, b_ih, b_hh);

    lstm_persist_kernel<<<NBLK, 256, smem_bytes>>>(W_hh);

    tag_kernel<<<SEQ, 288>>>(lin_w, lin_b);
    lsm_kernel<<<SEQ, 288>>>();
    crf_kernel<<<1, 288>>>(y, start_t, end_t, trans, out);
}

// round 5
// speedup vs baseline: 2.7068x; 1.7701x over previous
#include <cuda_runtime.h>
#include <cuda_bf16.h>
#include <math.h>
#include <stdint.h>

#define SEQ   200
#define BATCH 32
#define EMB   300
#define HID   1000
#define GH    4000   // 4*HID
#define TAGS  9

#define NBLK  125    // persistent blocks, 8 j-cols each; block owns kstep kk=bid
#define JB    8
#define NKK   125    // k-steps of 8 along HID
#define FRAG_PER_T (NKK * 2 * 32 * 4)   // 32000 floats per timestep

// ---------------- scratch ----------------
__device__ __align__(128) float g_xg   [SEQ * GH * BATCH];   // [t][n][b]
__device__ __align__(128) float g_hfrag[SEQ * FRAG_PER_T];   // mma A-fragment order
__device__ __align__(128) float g_hs   [SEQ * HID * BATCH];  // [t][j][b] for tag
__device__ float g_tag[SEQ * BATCH * TAGS];
__device__ unsigned g_cnt = 0;
__device__ unsigned g_gen = 0;

__device__ __forceinline__ float to_tf32(float v) {
    unsigned u;
    asm("cvt.rna.tf32.f32 %0, %1;" : "=r"(u) : "f"(v));
    return __uint_as_float(u);
}

__device__ __forceinline__ void mma_tf32(float* c, const uint4& a, const uint2& b) {
    asm volatile(
        "mma.sync.aligned.m16n8k8.row.col.f32.tf32.tf32.f32 "
        "{%0,%1,%2,%3},{%4,%5,%6,%7},{%8,%9},{%0,%1,%2,%3};"
        : "+f"(c[0]), "+f"(c[1]), "+f"(c[2]), "+f"(c[3])
        : "r"(a.x), "r"(a.y), "r"(a.z), "r"(a.w), "r"(b.x), "r"(b.y));
}

// ===========================================================================
// Kernel 1: xg[t][n][b] = dot(embed_w[x[t,b]], W_ih[n]) + b_ih[n] + b_hh[n]
// ===========================================================================
__global__ void xg_gemm_kernel(const int* __restrict__ x,
                               const float* __restrict__ embed_w,
                               const float* __restrict__ Wih,
                               const float* __restrict__ b_ih,
                               const float* __restrict__ b_hh)
{
    __shared__ __align__(16) float As[16][68];
    __shared__ __align__(16) float Bs[16][68];
    __shared__ int toks[64];

    const int tid = threadIdx.x;
    const int bm  = blockIdx.y * 64;
    const int bn  = blockIdx.x * 64;

    if (tid < 64) toks[tid] = x[bm + tid];
    __syncthreads();

    const int tx = tid & 15;
    const int ty = tid >> 4;
    const int lrow = tid >> 2;
    const int lk0  = (tid & 3) * 4;

    float acc[4][4];
#pragma unroll
    for (int i = 0; i < 4; i++)
#pragma unroll
        for (int j = 0; j < 4; j++) acc[i][j] = 0.f;

    const int ncol = bn + lrow;
    const float* wrow = Wih + (size_t)ncol * EMB;

    for (int k0 = 0; k0 < EMB; k0 += 16) {
        const float* erow = embed_w + (size_t)toks[lrow] * EMB;
#pragma unroll
        for (int i = 0; i < 4; i++) {
            int k = lk0 + i;
            As[k][lrow] = (k0 + k < EMB) ? erow[k0 + k] : 0.f;
            Bs[k][lrow] = (ncol < GH && k0 + k < EMB) ? wrow[k0 + k] : 0.f;
        }
        __syncthreads();
#pragma unroll
        for (int k = 0; k < 16; k++) {
            float4 a4 = *reinterpret_cast<const float4*>(&As[k][ty * 4]);
            float4 b4 = *reinterpret_cast<const float4*>(&Bs[k][tx * 4]);
            float ra[4] = {a4.x, a4.y, a4.z, a4.w};
            float rb[4] = {b4.x, b4.y, b4.z, b4.w};
#pragma unroll
            for (int i = 0; i < 4; i++)
#pragma unroll
                for (int j = 0; j < 4; j++) acc[i][j] += ra[i] * rb[j];
        }
        __syncthreads();
    }

#pragma unroll
    for (int i = 0; i < 4; i++) {
        int m = bm + ty * 4 + i;
        int t = m >> 5, b = m & 31;
#pragma unroll
        for (int j = 0; j < 4; j++) {
            int n = bn + tx * 4 + j;
            if (n < GH)
                g_xg[((size_t)t * GH + n) * BATCH + b] = acc[i][j] + b_ih[n] + b_hh[n];
        }
    }
}

// ===========================================================================
// Kernel 2: persistent tensor-core LSTM scan.
// 125 blocks x 256 threads, 1 block/SM.
//   - W slice packed in smem in B-fragment (tf32) order, loaded once.
//   - h stored globally in A-fragment order -> next step is pure LDG.128.
//   - 8 warps = 8 K-slices; each warp does all 2(m)x4(n) m16n8k8 tiles.
//   - 8-way K reduction via padded smem; grid barrier between steps.
// ===========================================================================
__global__ void __launch_bounds__(256, 1)
lstm_persist_mma(const float* __restrict__ Whh)
{
    extern __shared__ float sm[];
    float* w_fs = sm;          // 32000 words: [kk][nt][lane][2]
    float* red  = sm + 32000;  // 8704 words:  [ks(8)][b(32)][34]

    const int tid  = threadIdx.x;
    const int bid  = blockIdx.x;
    const int j0   = bid * JB;
    const int wid  = tid >> 5;
    const int lane = tid & 31;
    const int g    = lane >> 2;
    const int tig  = lane & 3;

    // combine-role mapping: thread owns (b=cb, j=j0+cjj)
    const int cb  = tid & 31;
    const int cjj = tid >> 5;
    const int j   = j0 + cjj;
    // h-fragment write index for (cb, j): kk = bid
    const int fmt   = cb >> 4;
    const int fr    = ((cb >> 3) & 1) + 2 * (cjj >> 2);
    const int flane = (cb & 7) * 4 + (cjj & 3);
    const int fidx  = ((bid * 2 + fmt) * 32 + flane) * 4 + fr;

    // ---- pack W slice into B-fragment order (tf32), once ----
    // word idx = kk*256 + nt*64 + lane*2 + r ; elem = Whh[(nt*HID + j0 + g)*HID + k]
    for (int idx = tid; idx < 32000; idx += 256) {
        int r  = idx & 1;
        int ln = (idx >> 1) & 31;
        int nt = (idx >> 6) & 3;
        int kk = idx >> 8;
        int k  = kk * 8 + (ln & 3) + r * 4;
        int rw = nt * HID + j0 + (ln >> 2);
        w_fs[idx] = to_tf32(Whh[(size_t)rw * HID + k]);
    }

    // per-warp K-slice bounds
    const int kb = (wid * NKK) >> 3;
    const int ke = ((wid + 1) * NKK) >> 3;

    float c_reg = 0.f;
    __syncthreads();

    for (int t = 0; t < SEQ; t++) {
        // prefetch xg gates early (DRAM latency hidden behind mma phase)
        const float* xgt = g_xg + (size_t)t * GH * BATCH;
        float gate[4];
#pragma unroll
        for (int gg = 0; gg < 4; gg++)
            gate[gg] = xgt[((size_t)(gg * HID + j)) * BATCH + cb];

        if (t > 0) {
            float c[2][4][4];
#pragma unroll
            for (int mt = 0; mt < 2; mt++)
#pragma unroll
                for (int nt = 0; nt < 4; nt++)
#pragma unroll
                    for (int rr = 0; rr < 4; rr++) c[mt][nt][rr] = 0.f;

            const uint4* hf = (const uint4*)(g_hfrag + (size_t)(t - 1) * FRAG_PER_T);
            const uint2* wv = (const uint2*)w_fs;

            uint4 a0 = hf[(kb * 2 + 0) * 32 + lane];
            uint4 a1 = hf[(kb * 2 + 1) * 32 + lane];

            for (int kk = kb; kk < ke; kk++) {
                uint4 n0, n1;
                if (kk + 1 < ke) {
                    n0 = hf[((kk + 1) * 2 + 0) * 32 + lane];
                    n1 = hf[((kk + 1) * 2 + 1) * 32 + lane];
                }
                uint2 bfr[4];
#pragma unroll
                for (int nt = 0; nt < 4; nt++)
                    bfr[nt] = wv[(kk * 4 + nt) * 32 + lane];
#pragma unroll
                for (int nt = 0; nt < 4; nt++) {
                    mma_tf32(c[0][nt], a0, bfr[nt]);
                    mma_tf32(c[1][nt], a1, bfr[nt]);
                }
                a0 = n0; a1 = n1;
            }

            // ---- stage K-slice partials: red[wid][b][34] ----
            float* myred = red + wid * 1088;
#pragma unroll
            for (int mt = 0; mt < 2; mt++) {
                const int b0 = mt * 16 + g;
#pragma unroll
                for (int nt = 0; nt < 4; nt++) {
                    const int col = nt * 8 + 2 * tig;
                    *(float2*)&myred[b0 * 34 + col]       = make_float2(c[mt][nt][0], c[mt][nt][1]);
                    *(float2*)&myred[(b0 + 8) * 34 + col] = make_float2(c[mt][nt][2], c[mt][nt][3]);
                }
            }
            __syncthreads();

            // ---- combine 8 slices ----
#pragma unroll
            for (int gg = 0; gg < 4; gg++) {
                float s = 0.f;
#pragma unroll
                for (int ks = 0; ks < 8; ks++)
                    s += red[ks * 1088 + cb * 34 + gg * 8 + cjj];
                gate[gg] += s;
            }
        }

        // ---- activations + state update ----
        {
            float iv = 1.f / (1.f + expf(-gate[0]));
            float fv = 1.f / (1.f + expf(-gate[1]));
            float gv = tanhf(gate[2]);
            float ov = 1.f / (1.f + expf(-gate[3]));
            c_reg = fv * c_reg + iv * gv;
            float hn = to_tf32(ov * tanhf(c_reg));
            g_hfrag[(size_t)t * FRAG_PER_T + fidx] = hn;
            g_hs[((size_t)t * HID + j) * BATCH + cb] = hn;
        }

        // ---- grid barrier (sense-reversing) ----
        __threadfence();
        __syncthreads();
        if (tid == 0) {
            unsigned my = atomicAdd(&g_gen, 0u);
            if (atomicAdd(&g_cnt, 1u) == NBLK - 1) {
                atomicExch(&g_cnt, 0u);
                __threadfence();
                atomicAdd(&g_gen, 1u);
            } else {
                while (*(volatile unsigned*)&g_gen == my) { }
            }
            __threadfence();
        }
        __syncthreads();
    }
}

// ===========================================================================
// Kernel 3: tag[t][b][k] = dot_j hs[t][j][b] * lin_w[k][j] + lin_b[k]
// ===========================================================================
__global__ void tag_kernel(const float* __restrict__ lin_w,
                           const float* __restrict__ lin_b)
{
    const int t = blockIdx.x;
    const int k = threadIdx.x >> 5;
    const int b = threadIdx.x & 31;
    const float* h = g_hs + (size_t)t * HID * BATCH;
    const float* w = lin_w + k * HID;
    float s = 0.f;
#pragma unroll 4
    for (int jj = 0; jj < HID; jj++) s += h[jj * BATCH + b] * w[jj];
    g_tag[(t * BATCH + b) * TAGS + k] = s + lin_b[k];
}

// ===========================================================================
// Kernel 4: log_softmax over BATCH axis (axis=1), in place.
// ===========================================================================
__global__ void lsm_kernel()
{
    const int t = blockIdx.x;
    const int k = threadIdx.x >> 5;
    const int b = threadIdx.x & 31;
    float v = g_tag[(t * BATCH + b) * TAGS + k];
    float m = v;
#pragma unroll
    for (int off = 16; off; off >>= 1) m = fmaxf(m, __shfl_xor_sync(0xffffffffu, m, off));
    float e = expf(v - m);
    float s = e;
#pragma unroll
    for (int off = 16; off; off >>= 1) s += __shfl_xor_sync(0xffffffffu, s, off);
    g_tag[(t * BATCH + b) * TAGS + k] = v - m - logf(s);
}

// ===========================================================================
// Kernel 5: CRF forward + numerator + final sum. single block.
// ===========================================================================
__global__ void crf_kernel(const int* __restrict__ y,
                           const float* __restrict__ start_t,
                           const float* __restrict__ end_t,
                           const float* __restrict__ trans,
                           float* __restrict__ out)
{
    __shared__ float alpha[BATCH][TAGS];
    __shared__ float tr[TAGS][TAGS];
    __shared__ float st[TAGS], en[TAGS];
    __shared__ float numer[BATCH], logz[BATCH];

    const int tid = threadIdx.x;
    if (tid < 81) tr[tid / 9][tid % 9] = trans[tid];
    if (tid < 9) { st[tid] = start_t[tid]; en[tid] = end_t[tid]; }
    __syncthreads();

    const int b = tid / 9, k = tid % 9;
    alpha[b][k] = st[k] + g_tag[(0 * BATCH + b) * TAGS + k];
    __syncthreads();

    for (int t = 1; t < SEQ; t++) {
        float av[9];
#pragma unroll
        for (int kp = 0; kp < 9; kp++) av[kp] = alpha[b][kp] + tr[kp][k];
        float m = av[0];
#pragma unroll
        for (int kp = 1; kp < 9; kp++) m = fmaxf(m, av[kp]);
        float s = 0.f;
#pragma unroll
        for (int kp = 0; kp < 9; kp++) s += expf(av[kp] - m);
        float nxt = m + logf(s) + g_tag[(t * BATCH + b) * TAGS + k];
        __syncthreads();
        alpha[b][k] = nxt;
        __syncthreads();
    }

    if (k == 0) {
        float m = alpha[b][0] + en[0];
#pragma unroll
        for (int kp = 1; kp < 9; kp++) m = fmaxf(m, alpha[b][kp] + en[kp]);
        float s = 0.f;
#pragma unroll
        for (int kp = 0; kp < 9; kp++) s += expf(alpha[b][kp] + en[kp] - m);
        logz[b] = m + logf(s);

        int yprev = y[0 * BATCH + b];
        float num = st[yprev] + g_tag[(0 * BATCH + b) * TAGS + yprev];
        for (int t = 1; t < SEQ; t++) {
            int yt = y[t * BATCH + b];
            num += tr[yprev][yt] + g_tag[(t * BATCH + b) * TAGS + yt];
            yprev = yt;
        }
        num += en[yprev];
        numer[b] = num;
    }
    __syncthreads();

    if (tid == 0) {
        float s = 0.f;
        for (int bb = 0; bb < BATCH; bb++) s += numer[bb] - logz[bb];
        out[0] = s;
    }
}

// ===========================================================================
// launch
// ===========================================================================
extern "C" void kernel_launch(void* const* d_in, const int* in_sizes, int n_in,
                              void* d_out, int out_size)
{
    const int*   x       = (const int*)  d_in[0];
    const int*   y       = (const int*)  d_in[1];
    const float* embed_w = (const float*)d_in[2];
    const float* W_ih    = (const float*)d_in[3];
    const float* W_hh    = (const float*)d_in[4];
    const float* b_ih    = (const float*)d_in[5];
    const float* b_hh    = (const float*)d_in[6];
    const float* lin_w   = (const float*)d_in[7];
    const float* lin_b   = (const float*)d_in[8];
    const float* start_t = (const float*)d_in[9];
    const float* end_t   = (const float*)d_in[10];
    const float* trans   = (const float*)d_in[11];
    float* out = (float*)d_out;

    const int smem_bytes = (32000 + 8704) * sizeof(float);   // 162816
    cudaFuncSetAttribute(lstm_persist_mma,
                         cudaFuncAttributeMaxDynamicSharedMemorySize, smem_bytes);

    xg_gemm_kernel<<<dim3(63, 100), 256>>>(x, embed_w, W_ih, b_ih, b_hh);

    lstm_persist_mma<<<NBLK, 256, smem_bytes>>>(W_hh);

    tag_kernel<<<SEQ, 288>>>(lin_w, lin_b);
    lsm_kernel<<<SEQ, 288>>>();
    crf_kernel<<<1, 288>>>(y, start_t, end_t, trans, out);
}

// round 6
// speedup vs baseline: 3.6200x; 1.3374x over previous
#include <cuda_runtime.h>
#include <cuda_bf16.h>
#include <math.h>
#include <stdint.h>

#define SEQ   200
#define BATCH 32
#define EMB   300
#define KPAD  304    // EMB padded to mult of 16
#define HID   1000
#define GH    4000   // 4*HID
#define TAGS  9

#define NBLK  125    // persistent blocks, 8 j-cols each; block owns kstep kk=bid
#define JB    8
#define NKK   125    // k-steps of 8 along HID
#define FRAG_PER_T (NKK * 2 * 32 * 4)   // 32000 floats per timestep

// ---------------- scratch ----------------
__device__ __align__(128) float g_xg   [SEQ * GH * BATCH];   // [t][n][b]
__device__ __align__(128) float g_hfrag[SEQ * FRAG_PER_T];   // mma A-fragment order
__device__ __align__(128) float g_hs   [SEQ * HID * BATCH];  // [t][j][b] for tag
__device__ float g_tag[SEQ * BATCH * TAGS];
__device__ __align__(128) float g_A   [6400 * KPAD];         // embeds, tf32, padded
__device__ __align__(128) float g_B   [GH * KPAD];           // W_ih,  tf32, padded
__device__ float g_bias[GH];                                  // b_ih + b_hh
__device__ volatile unsigned g_slot[NBLK * 32];               // barrier flags, 128B apart

__device__ __forceinline__ float to_tf32(float v) {
    unsigned u;
    asm("cvt.rna.tf32.f32 %0, %1;" : "=r"(u) : "f"(v));
    return __uint_as_float(u);
}

__device__ __forceinline__ void mma_tf32(float* c, const uint4& a, const uint2& b) {
    asm volatile(
        "mma.sync.aligned.m16n8k8.row.col.f32.tf32.tf32.f32 "
        "{%0,%1,%2,%3},{%4,%5,%6,%7},{%8,%9},{%0,%1,%2,%3};"
        : "+f"(c[0]), "+f"(c[1]), "+f"(c[2]), "+f"(c[3])
        : "r"(a.x), "r"(a.y), "r"(a.z), "r"(a.w), "r"(b.x), "r"(b.y));
}

// ===========================================================================
// Kernel 0: pack A (gathered embeddings) and B (W_ih) in tf32, K padded to 304;
// also fuse bias = b_ih + b_hh.
// ===========================================================================
__global__ void prep_kernel(const int* __restrict__ x,
                            const float* __restrict__ embed_w,
                            const float* __restrict__ Wih,
                            const float* __restrict__ b_ih,
                            const float* __restrict__ b_hh)
{
    const int NA = 6400 * KPAD;
    const int NB = GH * KPAD;
    const int stride = gridDim.x * blockDim.x;
    for (int i = blockIdx.x * blockDim.x + threadIdx.x; i < NA + NB + GH; i += stride) {
        if (i < NA) {
            int m = i / KPAD, k = i - m * KPAD;
            float v = 0.f;
            if (k < EMB) v = to_tf32(embed_w[(size_t)x[m] * EMB + k]);
            g_A[i] = v;
        } else if (i < NA + NB) {
            int idx = i - NA;
            int n = idx / KPAD, k = idx - n * KPAD;
            float v = 0.f;
            if (k < EMB) v = to_tf32(Wih[(size_t)n * EMB + k]);
            g_B[idx] = v;
        } else {
            int n = i - NA - NB;
            g_bias[n] = b_ih[n] + b_hh[n];
        }
    }
}

// ===========================================================================
// Kernel 1: xg = A @ B^T + bias, tf32 tensor cores.
// M=6400, N=4000, K=304. Block 128x128, 8 warps (2m x 4n), warp 64x32.
// Output written to g_xg[t][n][b] via smem-staged coalesced stores.
// ===========================================================================
__global__ void __launch_bounds__(256, 2)
xg_mma_kernel()
{
    __shared__ __align__(16) float smraw[5120];   // As[128][20] | Bs[128][20]; reused as epi [128][33]
    float* As = smraw;            // [m][k] stride 20
    float* Bs = smraw + 2560;     // [n][k] stride 20

    const int tid  = threadIdx.x;
    const int wid  = tid >> 5;
    const int lane = tid & 31;
    const int wm   = wid & 1;     // 0..1
    const int wn   = wid >> 1;    // 0..3
    const int bm   = blockIdx.y * 128;
    const int bn   = blockIdx.x * 128;

    float acc[4][4][4];
#pragma unroll
    for (int mt = 0; mt < 4; mt++)
#pragma unroll
        for (int nt = 0; nt < 4; nt++)
#pragma unroll
            for (int r = 0; r < 4; r++) acc[mt][nt][r] = 0.f;

    const int lrow = tid >> 1;
    const int lkc  = (tid & 1) * 8;
    const int nrow = bn + lrow;

    for (int k0 = 0; k0 < KPAD; k0 += 16) {
        // load A tile 128x16
        {
            const float* src = g_A + (size_t)(bm + lrow) * KPAD + k0 + lkc;
            float4 v0 = *(const float4*)(src);
            float4 v1 = *(const float4*)(src + 4);
            *(float4*)&As[lrow * 20 + lkc]     = v0;
            *(float4*)&As[lrow * 20 + lkc + 4] = v1;
        }
        // load B tile 128x16 (guard n)
        {
            float4 w0 = make_float4(0.f, 0.f, 0.f, 0.f), w1 = w0;
            if (nrow < GH) {
                const float* src = g_B + (size_t)nrow * KPAD + k0 + lkc;
                w0 = *(const float4*)(src);
                w1 = *(const float4*)(src + 4);
            }
            *(float4*)&Bs[lrow * 20 + lkc]     = w0;
            *(float4*)&Bs[lrow * 20 + lkc + 4] = w1;
        }
        __syncthreads();

#pragma unroll
        for (int k8 = 0; k8 < 2; k8++) {
            const int c = k8 * 8 + (lane & 3);
            uint4 af[4];
#pragma unroll
            for (int mt = 0; mt < 4; mt++) {
                int r = wm * 64 + mt * 16 + (lane >> 2);
                af[mt].x = __float_as_uint(As[r * 20 + c]);
                af[mt].y = __float_as_uint(As[(r + 8) * 20 + c]);
                af[mt].z = __float_as_uint(As[r * 20 + c + 4]);
                af[mt].w = __float_as_uint(As[(r + 8) * 20 + c + 4]);
            }
#pragma unroll
            for (int nt = 0; nt < 4; nt++) {
                int n = wn * 32 + nt * 8 + (lane >> 2);
                uint2 bf;
                bf.x = __float_as_uint(Bs[n * 20 + c]);
                bf.y = __float_as_uint(Bs[n * 20 + c + 4]);
#pragma unroll
                for (int mt = 0; mt < 4; mt++)
                    mma_tf32(acc[mt][nt], af[mt], bf);
            }
        }
        __syncthreads();
    }

    // ---- epilogue: stage 128m x 32n chunks through smem, store coalesced ----
    float* sm_e = smraw;   // [128][33]
    const int bt = bm >> 5;             // base t index (4 t's per block)
#pragma unroll
    for (int ch = 0; ch < 4; ch++) {
        if (wn == ch) {
#pragma unroll
            for (int mt = 0; mt < 4; mt++) {
                int row = wm * 64 + mt * 16 + (lane >> 2);
#pragma unroll
                for (int nt = 0; nt < 4; nt++) {
                    int col = nt * 8 + (lane & 3) * 2;
                    sm_e[row * 33 + col]           = acc[mt][nt][0];
                    sm_e[row * 33 + col + 1]       = acc[mt][nt][1];
                    sm_e[(row + 8) * 33 + col]     = acc[mt][nt][2];
                    sm_e[(row + 8) * 33 + col + 1] = acc[mt][nt][3];
                }
            }
        }
        __syncthreads();
#pragma unroll 4
        for (int task = wid; task < 128; task += 8) {
            int np = task >> 2, tt = task & 3;
            int n = bn + ch * 32 + np;
            if (n < GH)
                g_xg[((size_t)(bt + tt) * GH + n) * 32 + lane] =
                    sm_e[(tt * 32 + lane) * 33 + np] + g_bias[n];
        }
        __syncthreads();
    }
}

// ===========================================================================
// Kernel 2: persistent tensor-core LSTM scan (distributed flag barrier).
// ===========================================================================
__global__ void __launch_bounds__(256, 1)
lstm_persist_mma(const float* __restrict__ Whh)
{
    extern __shared__ float sm[];
    float* w_fs = sm;          // 32000 words: [kk][nt][lane][2]
    float* red  = sm + 32000;  // 8704 words:  [ks(8)][b(32)][34]

    const int tid  = threadIdx.x;
    const int bid  = blockIdx.x;
    const int j0   = bid * JB;
    const int wid  = tid >> 5;
    const int lane = tid & 31;
    const int g    = lane >> 2;
    const int tig  = lane & 3;

    const int cb  = tid & 31;
    const int cjj = tid >> 5;
    const int j   = j0 + cjj;
    const int fmt   = cb >> 4;
    const int fr    = ((cb >> 3) & 1) + 2 * (cjj >> 2);
    const int flane = (cb & 7) * 4 + (cjj & 3);
    const int fidx  = ((bid * 2 + fmt) * 32 + flane) * 4 + fr;

    // ---- pack W slice into B-fragment order (tf32), once ----
    for (int idx = tid; idx < 32000; idx += 256) {
        int r  = idx & 1;
        int ln = (idx >> 1) & 31;
        int nt = (idx >> 6) & 3;
        int kk = idx >> 8;
        int k  = kk * 8 + (ln & 3) + r * 4;
        int rw = nt * HID + j0 + (ln >> 2);
        w_fs[idx] = to_tf32(Whh[(size_t)rw * HID + k]);
    }

    const int kb = (wid * NKK) >> 3;
    const int ke = ((wid + 1) * NKK) >> 3;

    float c_reg = 0.f;
    __syncthreads();

    for (int t = 0; t < SEQ; t++) {
        const float* xgt = g_xg + (size_t)t * GH * BATCH;
        float gate[4];
#pragma unroll
        for (int gg = 0; gg < 4; gg++)
            gate[gg] = xgt[((size_t)(gg * HID + j)) * BATCH + cb];

        if (t > 0) {
            float c[2][4][4];
#pragma unroll
            for (int mt = 0; mt < 2; mt++)
#pragma unroll
                for (int nt = 0; nt < 4; nt++)
#pragma unroll
                    for (int rr = 0; rr < 4; rr++) c[mt][nt][rr] = 0.f;

            const uint4* hf = (const uint4*)(g_hfrag + (size_t)(t - 1) * FRAG_PER_T);
            const uint2* wv = (const uint2*)w_fs;

            uint4 a0 = hf[(kb * 2 + 0) * 32 + lane];
            uint4 a1 = hf[(kb * 2 + 1) * 32 + lane];

            for (int kk = kb; kk < ke; kk++) {
                uint4 n0, n1;
                if (kk + 1 < ke) {
                    n0 = hf[((kk + 1) * 2 + 0) * 32 + lane];
                    n1 = hf[((kk + 1) * 2 + 1) * 32 + lane];
                }
                uint2 bfr[4];
#pragma unroll
                for (int nt = 0; nt < 4; nt++)
                    bfr[nt] = wv[(kk * 4 + nt) * 32 + lane];
#pragma unroll
                for (int nt = 0; nt < 4; nt++) {
                    mma_tf32(c[0][nt], a0, bfr[nt]);
                    mma_tf32(c[1][nt], a1, bfr[nt]);
                }
                a0 = n0; a1 = n1;
            }

            float* myred = red + wid * 1088;
#pragma unroll
            for (int mt = 0; mt < 2; mt++) {
                const int b0 = mt * 16 + g;
#pragma unroll
                for (int nt = 0; nt < 4; nt++) {
                    const int col = nt * 8 + 2 * tig;
                    *(float2*)&myred[b0 * 34 + col]       = make_float2(c[mt][nt][0], c[mt][nt][1]);
                    *(float2*)&myred[(b0 + 8) * 34 + col] = make_float2(c[mt][nt][2], c[mt][nt][3]);
                }
            }
            __syncthreads();

#pragma unroll
            for (int gg = 0; gg < 4; gg++) {
                float s = 0.f;
#pragma unroll
                for (int ks = 0; ks < 8; ks++)
                    s += red[ks * 1088 + cb * 34 + gg * 8 + cjj];
                gate[gg] += s;
            }
        }

        {
            float iv = 1.f / (1.f + expf(-gate[0]));
            float fv = 1.f / (1.f + expf(-gate[1]));
            float gv = tanhf(gate[2]);
            float ov = 1.f / (1.f + expf(-gate[3]));
            c_reg = fv * c_reg + iv * gv;
            float hn = to_tf32(ov * tanhf(c_reg));
            g_hfrag[(size_t)t * FRAG_PER_T + fidx] = hn;
            g_hs[((size_t)t * HID + j) * BATCH + cb] = hn;
        }

        // ---- distributed flag barrier (skip after final step) ----
        if (t < SEQ - 1) {
            __syncthreads();                       // all h stores done block-wide
            if (tid == 0) {
                __threadfence();                   // publish to gpu scope
                g_slot[bid * 32] = (unsigned)(t + 1);
            }
            if (tid < NBLK) {
                while (g_slot[tid * 32] != (unsigned)(t + 1)) { }
                __threadfence();                   // acquire
            }
            __syncthreads();
        }
    }
}

// ===========================================================================
// Kernel 3: tag[t][b][k] = dot_j hs[t][j][b] * lin_w[k][j] + lin_b[k]
// ===========================================================================
__global__ void tag_kernel(const float* __restrict__ lin_w,
                           const float* __restrict__ lin_b)
{
    const int t = blockIdx.x;
    const int k = threadIdx.x >> 5;
    const int b = threadIdx.x & 31;
    const float* h = g_hs + (size_t)t * HID * BATCH;
    const float* w = lin_w + k * HID;
    float s0 = 0.f, s1 = 0.f, s2 = 0.f, s3 = 0.f;
#pragma unroll 2
    for (int jj = 0; jj < HID; jj += 4) {
        s0 += h[(jj + 0) * BATCH + b] * w[jj + 0];
        s1 += h[(jj + 1) * BATCH + b] * w[jj + 1];
        s2 += h[(jj + 2) * BATCH + b] * w[jj + 2];
        s3 += h[(jj + 3) * BATCH + b] * w[jj + 3];
    }
    g_tag[(t * BATCH + b) * TAGS + k] = (s0 + s1) + (s2 + s3) + lin_b[k];
}

// ===========================================================================
// Kernel 4: log_softmax over BATCH axis (axis=1), in place.
// ===========================================================================
__global__ void lsm_kernel()
{
    const int t = blockIdx.x;
    const int k = threadIdx.x >> 5;
    const int b = threadIdx.x & 31;
    float v = g_tag[(t * BATCH + b) * TAGS + k];
    float m = v;
#pragma unroll
    for (int off = 16; off; off >>= 1) m = fmaxf(m, __shfl_xor_sync(0xffffffffu, m, off));
    float e = expf(v - m);
    float s = e;
#pragma unroll
    for (int off = 16; off; off >>= 1) s += __shfl_xor_sync(0xffffffffu, s, off);
    g_tag[(t * BATCH + b) * TAGS + k] = v - m - logf(s);
}

// ===========================================================================
// Kernel 5: CRF forward + numerator + final sum. single block.
// ===========================================================================
__global__ void crf_kernel(const int* __restrict__ y,
                           const float* __restrict__ start_t,
                           const float* __restrict__ end_t,
                           const float* __restrict__ trans,
                           float* __restrict__ out)
{
    __shared__ float alpha[BATCH][TAGS];
    __shared__ float tr[TAGS][TAGS];
    __shared__ float st[TAGS], en[TAGS];
    __shared__ float numer[BATCH], logz[BATCH];

    const int tid = threadIdx.x;
    if (tid < 81) tr[tid / 9][tid % 9] = trans[tid];
    if (tid < 9) { st[tid] = start_t[tid]; en[tid] = end_t[tid]; }
    __syncthreads();

    const int b = tid / 9, k = tid % 9;
    alpha[b][k] = st[k] + g_tag[(0 * BATCH + b) * TAGS + k];
    __syncthreads();

    for (int t = 1; t < SEQ; t++) {
        float av[9];
#pragma unroll
        for (int kp = 0; kp < 9; kp++) av[kp] = alpha[b][kp] + tr[kp][k];
        float m = av[0];
#pragma unroll
        for (int kp = 1; kp < 9; kp++) m = fmaxf(m, av[kp]);
        float s = 0.f;
#pragma unroll
        for (int kp = 0; kp < 9; kp++) s += expf(av[kp] - m);
        float nxt = m + logf(s) + g_tag[(t * BATCH + b) * TAGS + k];
        __syncthreads();
        alpha[b][k] = nxt;
        __syncthreads();
    }

    if (k == 0) {
        float m = alpha[b][0] + en[0];
#pragma unroll
        for (int kp = 1; kp < 9; kp++) m = fmaxf(m, alpha[b][kp] + en[kp]);
        float s = 0.f;
#pragma unroll
        for (int kp = 0; kp < 9; kp++) s += expf(alpha[b][kp] + en[kp] - m);
        logz[b] = m + logf(s);

        int yprev = y[0 * BATCH + b];
        float num = st[yprev] + g_tag[(0 * BATCH + b) * TAGS + yprev];
        for (int t = 1; t < SEQ; t++) {
            int yt = y[t * BATCH + b];
            num += tr[yprev][yt] + g_tag[(t * BATCH + b) * TAGS + yt];
            yprev = yt;
        }
        num += en[yprev];
        numer[b] = num;
    }
    __syncthreads();

    if (tid == 0) {
        float s = 0.f;
        for (int bb = 0; bb < BATCH; bb++) s += numer[bb] - logz[bb];
        out[0] = s;
    }
}

// ===========================================================================
// launch
// ===========================================================================
extern "C" void kernel_launch(void* const* d_in, const int* in_sizes, int n_in,
                              void* d_out, int out_size)
{
    const int*   x       = (const int*)  d_in[0];
    const int*   y       = (const int*)  d_in[1];
    const float* embed_w = (const float*)d_in[2];
    const float* W_ih    = (const float*)d_in[3];
    const float* W_hh    = (const float*)d_in[4];
    const float* b_ih    = (const float*)d_in[5];
    const float* b_hh    = (const float*)d_in[6];
    const float* lin_w   = (const float*)d_in[7];
    const float* lin_b   = (const float*)d_in[8];
    const float* start_t = (const float*)d_in[9];
    const float* end_t   = (const float*)d_in[10];
    const float* trans   = (const float*)d_in[11];
    float* out = (float*)d_out;

    const int smem_bytes = (32000 + 8704) * sizeof(float);   // 162816
    cudaFuncSetAttribute(lstm_persist_mma,
                         cudaFuncAttributeMaxDynamicSharedMemorySize, smem_bytes);

    prep_kernel<<<4096, 256>>>(x, embed_w, W_ih, b_ih, b_hh);
    xg_mma_kernel<<<dim3(32, 50), 256>>>();

    lstm_persist_mma<<<NBLK, 256, smem_bytes>>>(W_hh);

    tag_kernel<<<SEQ, 288>>>(lin_w, lin_b);
    lsm_kernel<<<SEQ, 288>>>();
    crf_kernel<<<1, 288>>>(y, start_t, end_t, trans, out);
}

// round 9
// speedup vs baseline: 5.7299x; 1.5828x over previous
#include <cuda_runtime.h>
#include <cuda_fp16.h>
#include <math.h>
#include <stdint.h>

#define SEQ   200
#define BATCH 32
#define EMB   300
#define KPAD  304    // EMB padded to mult of 16
#define HID   1000
#define GH    4000   // 4*HID
#define TAGS  9

#define NBLK  125    // persistent blocks, 8 j-cols each
#define JB    8
#define NKT   63     // k-tiles of 16 (1008 = 63*16, padded)
#define FRAG16_PER_T (NKT * 2 * 32 * 4 * 2)   // 32256 halves per timestep

// ---------------- scratch ----------------
__device__ __align__(128) __half g_xg16  [SEQ * GH * BATCH];     // [t][n][b]
__device__ __align__(128) __half g_hfrag16[SEQ * FRAG16_PER_T];  // A-frag order (pad k zero-init)
__device__ __align__(128) __half g_hs16  [SEQ * HID * BATCH];    // [t][j][b]
__device__ float g_tag[SEQ * BATCH * TAGS];
__device__ __align__(128) __half g_A16[6400 * KPAD];             // embeds fp16
__device__ __align__(128) __half g_B16[GH * KPAD];               // W_ih fp16
__device__ float g_bias[GH];                                      // b_ih + b_hh
__device__ volatile unsigned g_slot[NBLK * 32];                   // barrier flags

__device__ __forceinline__ void mma_f16(float* c, const uint4& a, const uint2& b) {
    asm volatile(
        "mma.sync.aligned.m16n8k16.row.col.f32.f16.f16.f32 "
        "{%0,%1,%2,%3},{%4,%5,%6,%7},{%8,%9},{%0,%1,%2,%3};"
        : "+f"(c[0]), "+f"(c[1]), "+f"(c[2]), "+f"(c[3])
        : "r"(a.x), "r"(a.y), "r"(a.z), "r"(a.w), "r"(b.x), "r"(b.y));
}

// ===========================================================================
// Kernel 0: pack A (gathered embeds) and B (W_ih) in fp16, K padded to 304;
// bias = b_ih + b_hh.
// ===========================================================================
__global__ void prep_kernel(const int* __restrict__ x,
                            const float* __restrict__ embed_w,
                            const float* __restrict__ Wih,
                            const float* __restrict__ b_ih,
                            const float* __restrict__ b_hh)
{
    const int NA = 6400 * KPAD;
    const int NB = GH * KPAD;
    const int stride = gridDim.x * blockDim.x;
    for (int i = blockIdx.x * blockDim.x + threadIdx.x; i < NA + NB + GH; i += stride) {
        if (i < NA) {
            int m = i / KPAD, k = i - m * KPAD;
            __half v = __float2half(0.f);
            if (k < EMB) v = __float2half(embed_w[(size_t)x[m] * EMB + k]);
            g_A16[i] = v;
        } else if (i < NA + NB) {
            int idx = i - NA;
            int n = idx / KPAD, k = idx - n * KPAD;
            __half v = __float2half(0.f);
            if (k < EMB) v = __float2half(Wih[(size_t)n * EMB + k]);
            g_B16[idx] = v;
        } else {
            int n = i - NA - NB;
            g_bias[n] = b_ih[n] + b_hh[n];
        }
    }
}

// ===========================================================================
// Kernel 1: xg = A @ B^T + bias, fp16 mma m16n8k16.
// M=6400, N=4000, K=304. Block 128x128, 8 warps (2m x 4n), warp 64x32.
// Output g_xg16[t][n][b] (fp16) via smem-staged coalesced stores.
// ===========================================================================
__global__ void __launch_bounds__(256, 2)
xg_mma16_kernel()
{
    __shared__ __align__(16) float smraw[4224];    // 16896 B; reused for epilogue
    __half* As = (__half*)smraw;                   // [128][24]
    __half* Bs = As + 128 * 24;                    // [128][24]

    const int tid  = threadIdx.x;
    const int wid  = tid >> 5;
    const int lane = tid & 31;
    const int wm   = wid & 1;
    const int wn   = wid >> 1;
    const int gID  = lane >> 2;
    const int tig  = lane & 3;
    const int bm   = blockIdx.y * 128;
    const int bn   = blockIdx.x * 128;

    float acc[4][4][4];
#pragma unroll
    for (int mt = 0; mt < 4; mt++)
#pragma unroll
        for (int nt = 0; nt < 4; nt++)
#pragma unroll
            for (int r = 0; r < 4; r++) acc[mt][nt][r] = 0.f;

    const int lrow = tid >> 1;
    const int lk   = (tid & 1) * 8;
    const int nrow = bn + lrow;

    for (int k0 = 0; k0 < KPAD; k0 += 16) {
        *(uint4*)&As[lrow * 24 + lk] =
            *(const uint4*)(g_A16 + (size_t)(bm + lrow) * KPAD + k0 + lk);
        uint4 bv = make_uint4(0u, 0u, 0u, 0u);
        if (nrow < GH)
            bv = *(const uint4*)(g_B16 + (size_t)nrow * KPAD + k0 + lk);
        *(uint4*)&Bs[lrow * 24 + lk] = bv;
        __syncthreads();

        uint4 af[4];
#pragma unroll
        for (int mt = 0; mt < 4; mt++) {
            int r = wm * 64 + mt * 16 + gID;
            af[mt].x = *(const unsigned*)&As[r * 24 + tig * 2];
            af[mt].y = *(const unsigned*)&As[(r + 8) * 24 + tig * 2];
            af[mt].z = *(const unsigned*)&As[r * 24 + tig * 2 + 8];
            af[mt].w = *(const unsigned*)&As[(r + 8) * 24 + tig * 2 + 8];
        }
#pragma unroll
        for (int nt = 0; nt < 4; nt++) {
            int n = wn * 32 + nt * 8 + gID;
            uint2 bf;
            bf.x = *(const unsigned*)&Bs[n * 24 + tig * 2];
            bf.y = *(const unsigned*)&Bs[n * 24 + tig * 2 + 8];
#pragma unroll
            for (int mt = 0; mt < 4; mt++)
                mma_f16(acc[mt][nt], af[mt], bf);
        }
        __syncthreads();
    }

    // ---- epilogue: stage 128m x 32n chunks through smem, store coalesced ----
    float* sm_e = smraw;   // [128][33]
    const int bt = bm >> 5;
#pragma unroll
    for (int ch = 0; ch < 4; ch++) {
        if (wn == ch) {
#pragma unroll
            for (int mt = 0; mt < 4; mt++) {
                int row = wm * 64 + mt * 16 + gID;
#pragma unroll
                for (int nt = 0; nt < 4; nt++) {
                    int col = nt * 8 + tig * 2;
                    sm_e[row * 33 + col]           = acc[mt][nt][0];
                    sm_e[row * 33 + col + 1]       = acc[mt][nt][1];
                    sm_e[(row + 8) * 33 + col]     = acc[mt][nt][2];
                    sm_e[(row + 8) * 33 + col + 1] = acc[mt][nt][3];
                }
            }
        }
        __syncthreads();
#pragma unroll 4
        for (int task = wid; task < 128; task += 8) {
            int np = task >> 2, tt = task & 3;
            int n = bn + ch * 32 + np;
            if (n < GH)
                g_xg16[((size_t)(bt + tt) * GH + n) * 32 + lane] =
                    __float2half(sm_e[(tt * 32 + lane) * 33 + np] + g_bias[n]);
        }
        __syncthreads();
    }
}

// ===========================================================================
// Kernel 2: persistent fp16 tensor-core LSTM scan.
// 125 blocks x 256 threads, 1 block/SM. W in smem (fp16 B-frag order).
// h stored globally in fp16 A-frag order; all A-frags preloaded (MLP 16).
// ===========================================================================
__global__ void __launch_bounds__(256, 1)
lstm_persist_mma(const float* __restrict__ Whh)
{
    extern __shared__ float sm[];
    // w_fs: 16128 uint32 words (64512 B) : [kt][nt][lane][word]
    unsigned* w_fs = (unsigned*)sm;
    float* red = sm + 16128;   // 8704 floats: [ks(8)][b(32)][34]

    const int tid  = threadIdx.x;
    const int bid  = blockIdx.x;
    const int j0   = bid * JB;
    const int wid  = tid >> 5;
    const int lane = tid & 31;
    const int g    = lane >> 2;
    const int tig  = lane & 3;

    const int cb  = tid & 31;
    const int cjj = tid >> 5;
    const int j   = j0 + cjj;

    // h A-fragment (fp16) write index for (row=cb, k=j)
    const int kk2   = j >> 4;
    const int kp2   = j & 15;
    const int khi   = kp2 >> 3;
    const int pp    = kp2 & 1;
    const int tig2  = (kp2 >> 1) & 3;
    const int gID2  = cb & 7;
    const int rhi   = (cb >> 3) & 1;
    const int mt2   = cb >> 4;
    const int lane2 = gID2 * 4 + tig2;
    const int fidx16 = (((kk2 * 2 + mt2) * 32 + lane2) * 4 + (khi * 2 + rhi)) * 2 + pp;

    // ---- pack W slice into fp16 B-fragment order, once ----
    // word idx = kt*256 + nt*64 + ln*2 + wrd ; halves k = kt*16 + tig*2 + wrd*8 + {0,1}
    for (int idx = tid; idx < NKT * 256; idx += 256) {
        int wrd = idx & 1;
        int ln  = (idx >> 1) & 31;
        int nt  = (idx >> 6) & 3;
        int kt  = idx >> 8;
        int k0e = kt * 16 + (ln & 3) * 2 + wrd * 8;
        int rw  = nt * HID + j0 + (ln >> 2);
        float v0 = (k0e     < HID) ? Whh[(size_t)rw * HID + k0e]     : 0.f;
        float v1 = (k0e + 1 < HID) ? Whh[(size_t)rw * HID + k0e + 1] : 0.f;
        ((__half2*)w_fs)[idx] = __floats2half2_rn(v0, v1);
    }

    const int kb = wid * 8;   // warp 7 handles only 7 tiles (guarded)

    float c_reg = 0.f;
    __syncthreads();

    for (int t = 0; t < SEQ; t++) {
        // prefetch xg gates (fp16) early
        const __half* xgt = g_xg16 + (size_t)t * GH * BATCH;
        float gate[4];
#pragma unroll
        for (int gg = 0; gg < 4; gg++)
            gate[gg] = __half2float(xgt[((size_t)(gg * HID + j)) * BATCH + cb]);

        if (t > 0) {
            float c[2][4][4];
#pragma unroll
            for (int mt = 0; mt < 2; mt++)
#pragma unroll
                for (int nt = 0; nt < 4; nt++)
#pragma unroll
                    for (int rr = 0; rr < 4; rr++) c[mt][nt][rr] = 0.f;

            const uint4* hf = (const uint4*)(g_hfrag16 + (size_t)(t - 1) * FRAG16_PER_T);

            // batch-preload all A-fragments for this warp's k-slice (MLP 16)
            uint4 a[8][2];
#pragma unroll
            for (int i = 0; i < 8; i++) {
                int kk = kb + i;
                if (kk < NKT) {
                    a[i][0] = hf[(kk * 2 + 0) * 32 + lane];
                    a[i][1] = hf[(kk * 2 + 1) * 32 + lane];
                }
            }
            const uint2* wv = (const uint2*)w_fs;
#pragma unroll
            for (int i = 0; i < 8; i++) {
                int kk = kb + i;
                if (kk < NKT) {
                    uint2 bfr[4];
#pragma unroll
                    for (int nt = 0; nt < 4; nt++)
                        bfr[nt] = wv[(kk * 4 + nt) * 32 + lane];
#pragma unroll
                    for (int nt = 0; nt < 4; nt++) {
                        mma_f16(c[0][nt], a[i][0], bfr[nt]);
                        mma_f16(c[1][nt], a[i][1], bfr[nt]);
                    }
                }
            }

            // ---- stage K-slice partials: red[wid][b][34] ----
            float* myred = red + wid * 1088;
#pragma unroll
            for (int mt = 0; mt < 2; mt++) {
                const int b0 = mt * 16 + g;
#pragma unroll
                for (int nt = 0; nt < 4; nt++) {
                    const int col = nt * 8 + 2 * tig;
                    *(float2*)&myred[b0 * 34 + col]       = make_float2(c[mt][nt][0], c[mt][nt][1]);
                    *(float2*)&myred[(b0 + 8) * 34 + col] = make_float2(c[mt][nt][2], c[mt][nt][3]);
                }
            }
            __syncthreads();

#pragma unroll
            for (int gg = 0; gg < 4; gg++) {
                float s = 0.f;
#pragma unroll
                for (int ks = 0; ks < 8; ks++)
                    s += red[ks * 1088 + cb * 34 + gg * 8 + cjj];
                gate[gg] += s;
            }
        }

        // ---- activations + state update ----
        {
            float iv = 1.f / (1.f + expf(-gate[0]));
            float fv = 1.f / (1.f + expf(-gate[1]));
            float gv = tanhf(gate[2]);
            float ov = 1.f / (1.f + expf(-gate[3]));
            c_reg = fv * c_reg + iv * gv;
            float hn = ov * tanhf(c_reg);
            __half h16 = __float2half(hn);
            g_hfrag16[(size_t)t * FRAG16_PER_T + fidx16] = h16;
            g_hs16[((size_t)t * HID + j) * BATCH + cb] = h16;
        }

        // ---- distributed flag barrier (skip after final step) ----
        if (t < SEQ - 1) {
            __syncthreads();
            if (tid == 0) {
                __threadfence();
                g_slot[bid * 32] = (unsigned)(t + 1);
            }
            if (tid < NBLK) {
                while (g_slot[tid * 32] != (unsigned)(t + 1)) { }
                __threadfence();
            }
            __syncthreads();
        }
    }
}

// ===========================================================================
// Kernel 3: fused tag projection + log_softmax(axis=batch).
// block per t, 288 threads (9 warps). Warps 0-7: j-slices of 125 (lane=b),
// lin_w staged in smem; then smem reduce; then warp=k, lane=b log-softmax.
// ===========================================================================
__global__ void __launch_bounds__(288)
tag_lsm_kernel(const float* __restrict__ lin_w,
               const float* __restrict__ lin_b)
{
    __shared__ float w_sm[TAGS * HID];     // 36 KB
    __shared__ float part[8 * 32 * 10];    // 10.24 KB

    const int t   = blockIdx.x;
    const int tid = threadIdx.x;
    const int w   = tid >> 5;
    const int lane = tid & 31;

    for (int i = tid; i < TAGS * HID; i += 288) w_sm[i] = lin_w[i];
    __syncthreads();

    if (w < 8) {
        float acc[TAGS];
#pragma unroll
        for (int k = 0; k < TAGS; k++) acc[k] = 0.f;
        const __half* h = g_hs16 + (size_t)t * HID * BATCH;
        const int jbase = w * 125;
#pragma unroll 4
        for (int jj = 0; jj < 125; jj++) {
            int jcur = jbase + jj;
            float hv = __half2float(h[jcur * 32 + lane]);
#pragma unroll
            for (int k = 0; k < TAGS; k++)
                acc[k] += hv * w_sm[k * HID + jcur];
        }
#pragma unroll
        for (int k = 0; k < TAGS; k++)
            part[(w * 32 + lane) * 10 + k] = acc[k];
    }
    __syncthreads();

    // log-softmax over b (lane) for (k = warp)
    {
        const int k = w;     // 0..8
        const int b = lane;
        float v = lin_b[k];
#pragma unroll
        for (int ww = 0; ww < 8; ww++) v += part[(ww * 32 + b) * 10 + k];
        float m = v;
#pragma unroll
        for (int off = 16; off; off >>= 1) m = fmaxf(m, __shfl_xor_sync(0xffffffffu, m, off));
        float e = expf(v - m);
        float s = e;
#pragma unroll
        for (int off = 16; off; off >>= 1) s += __shfl_xor_sync(0xffffffffu, s, off);
        g_tag[(t * BATCH + b) * TAGS + k] = v - m - logf(s);
    }
}

// ===========================================================================
// Kernel 4: CRF forward + numerator + final sum. single block, 288 threads.
// Double-buffered alpha (1 sync/step); numerator parallel over (b, t-chunk).
// ===========================================================================
__global__ void crf_kernel(const int* __restrict__ y,
                           const float* __restrict__ start_t,
                           const float* __restrict__ end_t,
                           const float* __restrict__ trans,
                           float* __restrict__ out)
{
    __shared__ float alpha[2][BATCH][12];
    __shared__ float tr[TAGS][TAGS];
    __shared__ float st[TAGS], en[TAGS];
    __shared__ float numer_part[BATCH][TAGS];
    __shared__ float res[BATCH];

    const int tid = threadIdx.x;
    if (tid < 81) tr[tid / 9][tid % 9] = trans[tid];
    if (tid < 9) { st[tid] = start_t[tid]; en[tid] = end_t[tid]; }
    __syncthreads();

    const int b = tid / 9, k = tid % 9;

    // ---- numerator partial: chunk = k, t in [lo, hi) ----
    {
        int lo = k * 23, hi = min(SEQ, lo + 23);
        float s = 0.f;
        int yprev;
        if (k == 0) {
            int y0 = y[b];
            s += st[y0] + g_tag[b * TAGS + y0];
            yprev = y0;
            lo = 1;
        } else {
            yprev = y[(lo - 1) * BATCH + b];
        }
        for (int t = lo; t < hi; t++) {
            int yt = y[t * BATCH + b];
            s += tr[yprev][yt] + g_tag[(t * BATCH + b) * TAGS + yt];
            yprev = yt;
        }
        if (hi == SEQ) s += en[yprev];
        numer_part[b][k] = s;
    }

    // ---- alpha recursion (double-buffered) ----
    alpha[0][b][k] = st[k] + g_tag[b * TAGS + k];
    __syncthreads();
    int p = 0;
    for (int t = 1; t < SEQ; t++) {
        float av[9];
#pragma unroll
        for (int kp = 0; kp < 9; kp++) av[kp] = alpha[p][b][kp] + tr[kp][k];
        float m = av[0];
#pragma unroll
        for (int kp = 1; kp < 9; kp++) m = fmaxf(m, av[kp]);
        float s = 0.f;
#pragma unroll
        for (int kp = 0; kp < 9; kp++) s += expf(av[kp] - m);
        alpha[p ^ 1][b][k] = m + logf(s) + g_tag[(t * BATCH + b) * TAGS + k];
        p ^= 1;
        __syncthreads();
    }

    if (k == 0) {
        float m = alpha[p][b][0] + en[0];
#pragma unroll
        for (int kp = 1; kp < 9; kp++) m = fmaxf(m, alpha[p][b][kp] + en[kp]);
        float s = 0.f;
#pragma unroll
        for (int kp = 0; kp < 9; kp++) s += expf(alpha[p][b][kp] + en[kp] - m);
        float logz = m + logf(s);
        float num = 0.f;
#pragma unroll
        for (int c = 0; c < 9; c++) num += numer_part[b][c];
        res[b] = num - logz;
    }
    __syncthreads();

    if (tid == 0) {
        float s = 0.f;
        for (int bb = 0; bb < BATCH; bb++) s += res[bb];
        out[0] = s;
    }
}

// ===========================================================================
// launch
// ===========================================================================
extern "C" void kernel_launch(void* const* d_in, const int* in_sizes, int n_in,
                              void* d_out, int out_size)
{
    const int*   x       = (const int*)  d_in[0];
    const int*   y       = (const int*)  d_in[1];
    const float* embed_w = (const float*)d_in[2];
    const float* W_ih    = (const float*)d_in[3];
    const float* W_hh    = (const float*)d_in[4];
    const float* b_ih    = (const float*)d_in[5];
    const float* b_hh    = (const float*)d_in[6];
    const float* lin_w   = (const float*)d_in[7];
    const float* lin_b   = (const float*)d_in[8];
    const float* start_t = (const float*)d_in[9];
    const float* end_t   = (const float*)d_in[10];
    const float* trans   = (const float*)d_in[11];
    float* out = (float*)d_out;

    const int smem_bytes = 16128 * 4 + 8704 * 4;   // 99328
    cudaFuncSetAttribute(lstm_persist_mma,
                         cudaFuncAttributeMaxDynamicSharedMemorySize, smem_bytes);

    prep_kernel<<<4096, 256>>>(x, embed_w, W_ih, b_ih, b_hh);
    xg_mma16_kernel<<<dim3(32, 50), 256>>>();

    lstm_persist_mma<<<NBLK, 256, smem_bytes>>>(W_hh);

    tag_lsm_kernel<<<SEQ, 288>>>(lin_w, lin_b);
    crf_kernel<<<1, 288>>>(y, start_t, end_t, trans, out);
}

// round 10
// speedup vs baseline: 5.9131x; 1.0320x over previous
#include <cuda_runtime.h>
#include <cuda_fp16.h>
#include <math.h>
#include <stdint.h>

#define SEQ   200
#define BATCH 32
#define EMB   300
#define KPAD  304
#define HID   1000
#define GH    4000   // 4*HID
#define TAGS  9

#define NBLK  125    // persistent blocks, 8 j-cols each
#define JB    8
#define NKT   63     // k-tiles of 16 (1008 = 63*16, padded)
#define FRAG16_PER_T (NKT * 2 * 32 * 4 * 2)   // 32256 halves per timestep

// ---------------- scratch ----------------
__device__ __align__(128) __half g_xg16  [SEQ * GH * BATCH];     // [t][n][b]
__device__ __align__(128) __half g_hfrag16[SEQ * FRAG16_PER_T];  // A-frag order (pad zero-init)
__device__ __align__(128) __half g_hs16  [SEQ * HID * BATCH];    // [t][j][b]
__device__ float g_tag[SEQ * BATCH * TAGS];
__device__ volatile unsigned g_slot[NBLK * 32];                   // barrier flags

__device__ __forceinline__ void mma_f16(float* c, const uint4& a, const uint2& b) {
    asm volatile(
        "mma.sync.aligned.m16n8k16.row.col.f32.f16.f16.f32 "
        "{%0,%1,%2,%3},{%4,%5,%6,%7},{%8,%9},{%0,%1,%2,%3};"
        : "+f"(c[0]), "+f"(c[1]), "+f"(c[2]), "+f"(c[3])
        : "r"(a.x), "r"(a.y), "r"(a.z), "r"(a.w), "r"(b.x), "r"(b.y));
}

__device__ __forceinline__ float fast_tanh(float x) {
    float r; asm("tanh.approx.f32 %0, %1;" : "=f"(r) : "f"(x)); return r;
}
__device__ __forceinline__ float fast_sig(float x) {
    return 0.5f * fast_tanh(0.5f * x) + 0.5f;
}

__device__ __forceinline__ uint4 pack8h(float4 a, float4 b) {
    __half2 h0 = __floats2half2_rn(a.x, a.y);
    __half2 h1 = __floats2half2_rn(a.z, a.w);
    __half2 h2 = __floats2half2_rn(b.x, b.y);
    __half2 h3 = __floats2half2_rn(b.z, b.w);
    uint4 u;
    u.x = *(unsigned*)&h0; u.y = *(unsigned*)&h1;
    u.z = *(unsigned*)&h2; u.w = *(unsigned*)&h3;
    return u;
}

// ===========================================================================
// Kernel 1: xg = embed_w[x] @ W_ih^T + (b_ih+b_hh), fused gather+convert,
// fp16 mma m16n8k16, double-buffered smem (1 sync per k-iter).
// M=6400, N=4000, K=304. Block 128x128, 8 warps (2m x 4n).
// Output g_xg16[t][n][b] via smem-staged coalesced stores.
// ===========================================================================
__global__ void __launch_bounds__(256, 2)
xg_fused_kernel(const int* __restrict__ x,
                const float* __restrict__ embed_w,
                const float* __restrict__ Wih,
                const float* __restrict__ b_ih,
                const float* __restrict__ b_hh)
{
    __shared__ __align__(16) float smraw[6144];    // 24576 B, reused for epilogue
    __shared__ int toks[128];
    __half* hb = (__half*)smraw;                   // A(buf)=hb+buf*6144, B=+3072

    const int tid  = threadIdx.x;
    const int wid  = tid >> 5;
    const int lane = tid & 31;
    const int wm   = wid & 1;
    const int wn   = wid >> 1;
    const int gID  = lane >> 2;
    const int tig  = lane & 3;
    const int bm   = blockIdx.y * 128;
    const int bn   = blockIdx.x * 128;

    if (tid < 128) toks[tid] = x[bm + tid];
    __syncthreads();

    const int lrow = tid >> 1;
    const int lk   = (tid & 1) * 8;
    const int nrow = bn + lrow;
    const bool bvalid = (nrow < GH);
    const float* asrc = embed_w + (size_t)toks[lrow] * EMB;
    const float* wsrc = Wih + (size_t)(bvalid ? nrow : 0) * EMB;

    float acc[4][4][4];
#pragma unroll
    for (int mt = 0; mt < 4; mt++)
#pragma unroll
        for (int nt = 0; nt < 4; nt++)
#pragma unroll
            for (int r = 0; r < 4; r++) acc[mt][nt][r] = 0.f;

    const float4 z4 = make_float4(0.f, 0.f, 0.f, 0.f);
    float4 ra0, ra1, rb0, rb1;

    // load tile 0
    {
        int base = lk;
        ra0 = *(const float4*)(asrc + base);
        ra1 = *(const float4*)(asrc + base + 4);
        rb0 = bvalid ? *(const float4*)(wsrc + base) : z4;
        rb1 = bvalid ? *(const float4*)(wsrc + base + 4) : z4;
    }
    *(uint4*)&hb[0 * 6144 + lrow * 24 + lk]        = pack8h(ra0, ra1);
    *(uint4*)&hb[0 * 6144 + 3072 + lrow * 24 + lk] = pack8h(rb0, rb1);
    __syncthreads();

    const int NT = KPAD / 16;   // 19
    for (int kt = 0; kt < NT; kt++) {
        const int cur = kt & 1;
        if (kt + 1 < NT) {
            int base = (kt + 1) * 16 + lk;
            bool v1 = (base + 7 < EMB);
            ra0 = *(const float4*)(asrc + base);
            ra1 = v1 ? *(const float4*)(asrc + base + 4) : z4;
            rb0 = bvalid ? *(const float4*)(wsrc + base) : z4;
            rb1 = (bvalid && v1) ? *(const float4*)(wsrc + base + 4) : z4;
        }

        const __half* Ab = hb + cur * 6144;
        const __half* Bb = Ab + 3072;
        uint4 af[4];
#pragma unroll
        for (int mt = 0; mt < 4; mt++) {
            int r = wm * 64 + mt * 16 + gID;
            af[mt].x = *(const unsigned*)&Ab[r * 24 + tig * 2];
            af[mt].y = *(const unsigned*)&Ab[(r + 8) * 24 + tig * 2];
            af[mt].z = *(const unsigned*)&Ab[r * 24 + tig * 2 + 8];
            af[mt].w = *(const unsigned*)&Ab[(r + 8) * 24 + tig * 2 + 8];
        }
#pragma unroll
        for (int nt = 0; nt < 4; nt++) {
            int n = wn * 32 + nt * 8 + gID;
            uint2 bf;
            bf.x = *(const unsigned*)&Bb[n * 24 + tig * 2];
            bf.y = *(const unsigned*)&Bb[n * 24 + tig * 2 + 8];
#pragma unroll
            for (int mt = 0; mt < 4; mt++)
                mma_f16(acc[mt][nt], af[mt], bf);
        }

        if (kt + 1 < NT) {
            __half* An = hb + (cur ^ 1) * 6144;
            *(uint4*)&An[lrow * 24 + lk]        = pack8h(ra0, ra1);
            *(uint4*)&An[3072 + lrow * 24 + lk] = pack8h(rb0, rb1);
            __syncthreads();
        }
    }
    __syncthreads();

    // ---- epilogue: stage 128m x 32n chunks through smem, store coalesced ----
    float* sm_e = smraw;   // [128][33]
    const int bt = bm >> 5;
#pragma unroll
    for (int ch = 0; ch < 4; ch++) {
        if (wn == ch) {
#pragma unroll
            for (int mt = 0; mt < 4; mt++) {
                int row = wm * 64 + mt * 16 + gID;
#pragma unroll
                for (int nt = 0; nt < 4; nt++) {
                    int col = nt * 8 + tig * 2;
                    sm_e[row * 33 + col]           = acc[mt][nt][0];
                    sm_e[row * 33 + col + 1]       = acc[mt][nt][1];
                    sm_e[(row + 8) * 33 + col]     = acc[mt][nt][2];
                    sm_e[(row + 8) * 33 + col + 1] = acc[mt][nt][3];
                }
            }
        }
        __syncthreads();
#pragma unroll 4
        for (int task = wid; task < 128; task += 8) {
            int np = task >> 2, tt = task & 3;
            int n = bn + ch * 32 + np;
            if (n < GH) {
                float bias = b_ih[n] + b_hh[n];
                g_xg16[((size_t)(bt + tt) * GH + n) * 32 + lane] =
                    __float2half(sm_e[(tt * 32 + lane) * 33 + np] + bias);
            }
        }
        __syncthreads();
    }
}

// ===========================================================================
// Kernel 2: persistent fp16 tensor-core LSTM scan.
// Split per-warp barrier: warps 0-3 wait on producers of j<512 (blocks 0-63),
// warps 4-7 on blocks 64-124. Gate loads for t+1 issued before the poll.
// ===========================================================================
__global__ void __launch_bounds__(256, 1)
lstm_persist_mma(const float* __restrict__ Whh)
{
    extern __shared__ float sm[];
    unsigned* w_fs = (unsigned*)sm;   // 16128 words: [kt][nt][lane][word]
    float* red = sm + 16128;          // 8704 floats: [ks(8)][b(32)][34]

    const int tid  = threadIdx.x;
    const int bid  = blockIdx.x;
    const int j0   = bid * JB;
    const int wid  = tid >> 5;
    const int lane = tid & 31;
    const int g    = lane >> 2;
    const int tig  = lane & 3;

    const int cb  = tid & 31;
    const int cjj = tid >> 5;
    const int j   = j0 + cjj;

    // h A-fragment (fp16) write index for (row=cb, k=j)
    const int kk2   = j >> 4;
    const int kp2   = j & 15;
    const int khi   = kp2 >> 3;
    const int pp    = kp2 & 1;
    const int tig2  = (kp2 >> 1) & 3;
    const int gID2  = cb & 7;
    const int rhi   = (cb >> 3) & 1;
    const int mt2   = cb >> 4;
    const int lane2 = gID2 * 4 + tig2;
    const int fidx16 = (((kk2 * 2 + mt2) * 32 + lane2) * 4 + (khi * 2 + rhi)) * 2 + pp;

    // ---- pack W slice into fp16 B-fragment order, once ----
    for (int idx = tid; idx < NKT * 256; idx += 256) {
        int wrd = idx & 1;
        int ln  = (idx >> 1) & 31;
        int nt  = (idx >> 6) & 3;
        int kt  = idx >> 8;
        int k0e = kt * 16 + (ln & 3) * 2 + wrd * 8;
        int rw  = nt * HID + j0 + (ln >> 2);
        float v0 = (k0e     < HID) ? Whh[(size_t)rw * HID + k0e]     : 0.f;
        float v1 = (k0e + 1 < HID) ? Whh[(size_t)rw * HID + k0e + 1] : 0.f;
        ((__half2*)w_fs)[idx] = __floats2half2_rn(v0, v1);
    }

    const int kb = wid * 8;   // warp 7: only 7 tiles (guarded)

    float c_reg = 0.f;
    float gate[4];
    // prefetch t=0 gates
#pragma unroll
    for (int gg = 0; gg < 4; gg++)
        gate[gg] = __half2float(g_xg16[((size_t)(gg * HID + j)) * BATCH + cb]);
    __syncthreads();

    for (int t = 0; t < SEQ; t++) {
        if (t > 0) {
            // ---- per-warp split barrier poll ----
            const unsigned want = (unsigned)t;
            if (wid < 4) {
                while (g_slot[lane * 32] != want) { }
                while (g_slot[(lane + 32) * 32] != want) { }
            } else {
                while (g_slot[(64 + lane) * 32] != want) { }
                if (lane < 29) { while (g_slot[(96 + lane) * 32] != want) { } }
            }
            __threadfence();   // acquire

            float c[2][4][4];
#pragma unroll
            for (int mt = 0; mt < 2; mt++)
#pragma unroll
                for (int nt = 0; nt < 4; nt++)
#pragma unroll
                    for (int rr = 0; rr < 4; rr++) c[mt][nt][rr] = 0.f;

            const uint4* hf = (const uint4*)(g_hfrag16 + (size_t)(t - 1) * FRAG16_PER_T);

            uint4 a[8][2];
#pragma unroll
            for (int i = 0; i < 8; i++) {
                int kk = kb + i;
                if (kk < NKT) {
                    a[i][0] = hf[(kk * 2 + 0) * 32 + lane];
                    a[i][1] = hf[(kk * 2 + 1) * 32 + lane];
                }
            }
            const uint2* wv = (const uint2*)w_fs;
#pragma unroll
            for (int i = 0; i < 8; i++) {
                int kk = kb + i;
                if (kk < NKT) {
                    uint2 bfr[4];
#pragma unroll
                    for (int nt = 0; nt < 4; nt++)
                        bfr[nt] = wv[(kk * 4 + nt) * 32 + lane];
#pragma unroll
                    for (int nt = 0; nt < 4; nt++) {
                        mma_f16(c[0][nt], a[i][0], bfr[nt]);
                        mma_f16(c[1][nt], a[i][1], bfr[nt]);
                    }
                }
            }

            // ---- stage K-slice partials ----
            float* myred = red + wid * 1088;
#pragma unroll
            for (int mt = 0; mt < 2; mt++) {
                const int b0 = mt * 16 + g;
#pragma unroll
                for (int nt = 0; nt < 4; nt++) {
                    const int col = nt * 8 + 2 * tig;
                    *(float2*)&myred[b0 * 34 + col]       = make_float2(c[mt][nt][0], c[mt][nt][1]);
                    *(float2*)&myred[(b0 + 8) * 34 + col] = make_float2(c[mt][nt][2], c[mt][nt][3]);
                }
            }
            __syncthreads();

#pragma unroll
            for (int gg = 0; gg < 4; gg++) {
                float s = 0.f;
#pragma unroll
                for (int ks = 0; ks < 8; ks++)
                    s += red[ks * 1088 + cb * 34 + gg * 8 + cjj];
                gate[gg] += s;
            }
        }

        // ---- activations + state update ----
        {
            float iv = fast_sig(gate[0]);
            float fv = fast_sig(gate[1]);
            float gv = fast_tanh(gate[2]);
            float ov = fast_sig(gate[3]);
            c_reg = fv * c_reg + iv * gv;
            float hn = ov * fast_tanh(c_reg);
            __half h16 = __float2half(hn);
            g_hfrag16[(size_t)t * FRAG16_PER_T + fidx16] = h16;
            g_hs16[((size_t)t * HID + j) * BATCH + cb] = h16;
        }

        __syncthreads();    // all h stores done block-wide; also protects red reuse

        if (t < SEQ - 1) {
            if (tid == 0) {
                __threadfence();
                g_slot[bid * 32] = (unsigned)(t + 1);
            }
            // prefetch next-step gates (in flight during next poll)
            const __half* xgt = g_xg16 + (size_t)(t + 1) * GH * BATCH;
#pragma unroll
            for (int gg = 0; gg < 4; gg++)
                gate[gg] = __half2float(xgt[((size_t)(gg * HID + j)) * BATCH + cb]);
        }
    }
}

// ===========================================================================
// Kernel 3: fused tag projection + log_softmax(axis=batch).
// block per t, 288 threads. Warps 0-7: j-chunks of 128/104 (lane=b),
// register-blocked x4 with float4 lin_w reads.
// ===========================================================================
__global__ void __launch_bounds__(288)
tag_lsm_kernel(const float* __restrict__ lin_w,
               const float* __restrict__ lin_b)
{
    __shared__ float w_sm[TAGS * HID];     // 36 KB
    __shared__ float part[8 * 32 * 10];    // 10.24 KB

    const int t    = blockIdx.x;
    const int tid  = threadIdx.x;
    const int w    = tid >> 5;
    const int lane = tid & 31;

    for (int i = tid; i < TAGS * HID; i += 288) w_sm[i] = lin_w[i];
    __syncthreads();

    if (w < 8) {
        float acc[TAGS];
#pragma unroll
        for (int k = 0; k < TAGS; k++) acc[k] = 0.f;
        const __half* h = g_hs16 + (size_t)t * HID * BATCH;
        const int jbase = w * 128;
        const int jcnt  = (w < 7) ? 128 : 104;
#pragma unroll 2
        for (int jj = 0; jj < jcnt; jj += 4) {
            const int j4 = jbase + jj;
            float hv0 = __half2float(h[(j4 + 0) * 32 + lane]);
            float hv1 = __half2float(h[(j4 + 1) * 32 + lane]);
            float hv2 = __half2float(h[(j4 + 2) * 32 + lane]);
            float hv3 = __half2float(h[(j4 + 3) * 32 + lane]);
#pragma unroll
            for (int k = 0; k < TAGS; k++) {
                float4 wv = *(const float4*)&w_sm[k * HID + j4];
                acc[k] += hv0 * wv.x + hv1 * wv.y + hv2 * wv.z + hv3 * wv.w;
            }
        }
#pragma unroll
        for (int k = 0; k < TAGS; k++)
            part[(w * 32 + lane) * 10 + k] = acc[k];
    }
    __syncthreads();

    {
        const int k = w;     // 0..8
        const int b = lane;
        float v = lin_b[k];
#pragma unroll
        for (int ww = 0; ww < 8; ww++) v += part[(ww * 32 + b) * 10 + k];
        float m = v;
#pragma unroll
        for (int off = 16; off; off >>= 1) m = fmaxf(m, __shfl_xor_sync(0xffffffffu, m, off));
        float e = __expf(v - m);
        float s = e;
#pragma unroll
        for (int off = 16; off; off >>= 1) s += __shfl_xor_sync(0xffffffffu, s, off);
        g_tag[(t * BATCH + b) * TAGS + k] = v - m - __logf(s);
    }
}

// ===========================================================================
// Kernel 4: CRF forward + numerator + final sum. single block, 288 threads.
// ===========================================================================
__global__ void crf_kernel(const int* __restrict__ y,
                           const float* __restrict__ start_t,
                           const float* __restrict__ end_t,
                           const float* __restrict__ trans,
                           float* __restrict__ out)
{
    __shared__ float alpha[2][BATCH][12];
    __shared__ float tr[TAGS][TAGS];
    __shared__ float st[TAGS], en[TAGS];
    __shared__ float numer_part[BATCH][TAGS];
    __shared__ float res[BATCH];

    const int tid = threadIdx.x;
    if (tid < 81) tr[tid / 9][tid % 9] = trans[tid];
    if (tid < 9) { st[tid] = start_t[tid]; en[tid] = end_t[tid]; }
    __syncthreads();

    const int b = tid / 9, k = tid % 9;

    // ---- numerator partial: chunk = k, t in [lo, hi) ----
    {
        int lo = k * 23, hi = min(SEQ, lo + 23);
        float s = 0.f;
        int yprev;
        if (k == 0) {
            int y0 = y[b];
            s += st[y0] + g_tag[b * TAGS + y0];
            yprev = y0;
            lo = 1;
        } else {
            yprev = y[(lo - 1) * BATCH + b];
        }
        for (int t = lo; t < hi; t++) {
            int yt = y[t * BATCH + b];
            s += tr[yprev][yt] + g_tag[(t * BATCH + b) * TAGS + yt];
            yprev = yt;
        }
        if (hi == SEQ) s += en[yprev];
        numer_part[b][k] = s;
    }

    // ---- alpha recursion (double-buffered) ----
    alpha[0][b][k] = st[k] + g_tag[b * TAGS + k];
    __syncthreads();
    int p = 0;
    for (int t = 1; t < SEQ; t++) {
        float av[9];
#pragma unroll
        for (int kp = 0; kp < 9; kp++) av[kp] = alpha[p][b][kp] + tr[kp][k];
        float m = av[0];
#pragma unroll
        for (int kp = 1; kp < 9; kp++) m = fmaxf(m, av[kp]);
        float s = 0.f;
#pragma unroll
        for (int kp = 0; kp < 9; kp++) s += __expf(av[kp] - m);
        alpha[p ^ 1][b][k] = m + __logf(s) + g_tag[(t * BATCH + b) * TAGS + k];
        p ^= 1;
        __syncthreads();
    }

    if (k == 0) {
        float m = alpha[p][b][0] + en[0];
#pragma unroll
        for (int kp = 1; kp < 9; kp++) m = fmaxf(m, alpha[p][b][kp] + en[kp]);
        float s = 0.f;
#pragma unroll
        for (int kp = 0; kp < 9; kp++) s += __expf(alpha[p][b][kp] + en[kp] - m);
        float logz = m + __logf(s);
        float num = 0.f;
#pragma unroll
        for (int c = 0; c < 9; c++) num += numer_part[b][c];
        res[b] = num - logz;
    }
    __syncthreads();

    if (tid == 0) {
        float s = 0.f;
        for (int bb = 0; bb < BATCH; bb++) s += res[bb];
        out[0] = s;
    }
}

// ===========================================================================
// launch
// ===========================================================================
extern "C" void kernel_launch(void* const* d_in, const int* in_sizes, int n_in,
                              void* d_out, int out_size)
{
    const int*   x       = (const int*)  d_in[0];
    const int*   y       = (const int*)  d_in[1];
    const float* embed_w = (const float*)d_in[2];
    const float* W_ih    = (const float*)d_in[3];
    const float* W_hh    = (const float*)d_in[4];
    const float* b_ih    = (const float*)d_in[5];
    const float* b_hh    = (const float*)d_in[6];
    const float* lin_w   = (const float*)d_in[7];
    const float* lin_b   = (const float*)d_in[8];
    const float* start_t = (const float*)d_in[9];
    const float* end_t   = (const float*)d_in[10];
    const float* trans   = (const float*)d_in[11];
    float* out = (float*)d_out;

    const int smem_bytes = 16128 * 4 + 8704 * 4;   // 99328
    cudaFuncSetAttribute(lstm_persist_mma,
                         cudaFuncAttributeMaxDynamicSharedMemorySize, smem_bytes);

    xg_fused_kernel<<<dim3(32, 50), 256>>>(x, embed_w, W_ih, b_ih, b_hh);

    lstm_persist_mma<<<NBLK, 256, smem_bytes>>>(W_hh);

    tag_lsm_kernel<<<SEQ, 288>>>(lin_w, lin_b);
    crf_kernel<<<1, 288>>>(y, start_t, end_t, trans, out);
}

// round 13
// speedup vs baseline: 8.2494x; 1.3951x over previous
#include <cuda_runtime.h>
#include <cuda_fp16.h>
#include <math.h>
#include <stdint.h>

#define SEQ   200
#define BATCH 32
#define EMB   300
#define KPAD  304
#define HID   1000
#define GH    4000   // 4*HID
#define TAGS  9

#define NBLK  125    // persistent blocks, 8 j-cols each
#define JB    8
#define NKT   63     // k-tiles of 16 (1008 = 63*16, padded)
#define FRAG16_PER_T (NKT * 2 * 32 * 4 * 2)   // 32256 halves per timestep

// ---------------- scratch ----------------
__device__ __align__(128) __half g_xg16  [SEQ * GH * BATCH];     // [t][n][b]
__device__ __align__(128) __half g_hfrag16[SEQ * FRAG16_PER_T];  // A-frag order (pad zero-init)
__device__ __align__(128) __half g_hs16  [SEQ * HID * BATCH];    // [t][j][b]
__device__ float g_tag[SEQ * BATCH * TAGS];
__device__ unsigned g_slot[NBLK * 32];                            // barrier flags (128B apart)

__device__ __forceinline__ void mma_f16(float* c, const uint4& a, const uint2& b) {
    asm volatile(
        "mma.sync.aligned.m16n8k16.row.col.f32.f16.f16.f32 "
        "{%0,%1,%2,%3},{%4,%5,%6,%7},{%8,%9},{%0,%1,%2,%3};"
        : "+f"(c[0]), "+f"(c[1]), "+f"(c[2]), "+f"(c[3])
        : "r"(a.x), "r"(a.y), "r"(a.z), "r"(a.w), "r"(b.x), "r"(b.y));
}

__device__ __forceinline__ float fast_tanh(float x) {
    float r; asm("tanh.approx.f32 %0, %1;" : "=f"(r) : "f"(x)); return r;
}
__device__ __forceinline__ float fast_sig(float x) {
    return 0.5f * fast_tanh(0.5f * x) + 0.5f;
}

__device__ __forceinline__ uint4 pack8h(float4 a, float4 b) {
    __half2 h0 = __floats2half2_rn(a.x, a.y);
    __half2 h1 = __floats2half2_rn(a.z, a.w);
    __half2 h2 = __floats2half2_rn(b.x, b.y);
    __half2 h3 = __floats2half2_rn(b.z, b.w);
    uint4 u;
    u.x = *(unsigned*)&h0; u.y = *(unsigned*)&h1;
    u.z = *(unsigned*)&h2; u.w = *(unsigned*)&h3;
    return u;
}

__device__ __forceinline__ void flag_release(unsigned* p, unsigned v) {
    asm volatile("st.release.gpu.global.u32 [%0], %1;" :: "l"(p), "r"(v) : "memory");
}
__device__ __forceinline__ unsigned flag_acquire(const unsigned* p) {
    unsigned v;
    asm volatile("ld.acquire.gpu.global.u32 %0, [%1];" : "=r"(v) : "l"(p) : "memory");
    return v;
}

// ===========================================================================
// Kernel 1: xg = embed_w[x] @ W_ih^T + (b_ih+b_hh), fused gather+convert,
// fp16 mma m16n8k16, double-buffered smem.
// ===========================================================================
__global__ void __launch_bounds__(256, 2)
xg_fused_kernel(const int* __restrict__ x,
                const float* __restrict__ embed_w,
                const float* __restrict__ Wih,
                const float* __restrict__ b_ih,
                const float* __restrict__ b_hh)
{
    __shared__ __align__(16) float smraw[6144];
    __shared__ int toks[128];
    __half* hb = (__half*)smraw;

    const int tid  = threadIdx.x;
    const int wid  = tid >> 5;
    const int lane = tid & 31;
    const int wm   = wid & 1;
    const int wn   = wid >> 1;
    const int gID  = lane >> 2;
    const int tig  = lane & 3;
    const int bm   = blockIdx.y * 128;
    const int bn   = blockIdx.x * 128;

    if (tid < 128) toks[tid] = x[bm + tid];
    __syncthreads();

    const int lrow = tid >> 1;
    const int lk   = (tid & 1) * 8;
    const int nrow = bn + lrow;
    const bool bvalid = (nrow < GH);
    const float* asrc = embed_w + (size_t)toks[lrow] * EMB;
    const float* wsrc = Wih + (size_t)(bvalid ? nrow : 0) * EMB;

    float acc[4][4][4];
#pragma unroll
    for (int mt = 0; mt < 4; mt++)
#pragma unroll
        for (int nt = 0; nt < 4; nt++)
#pragma unroll
            for (int r = 0; r < 4; r++) acc[mt][nt][r] = 0.f;

    const float4 z4 = make_float4(0.f, 0.f, 0.f, 0.f);
    float4 ra0, ra1, rb0, rb1;

    {
        ra0 = *(const float4*)(asrc + lk);
        ra1 = *(const float4*)(asrc + lk + 4);
        rb0 = bvalid ? *(const float4*)(wsrc + lk) : z4;
        rb1 = bvalid ? *(const float4*)(wsrc + lk + 4) : z4;
    }
    *(uint4*)&hb[lrow * 24 + lk]        = pack8h(ra0, ra1);
    *(uint4*)&hb[3072 + lrow * 24 + lk] = pack8h(rb0, rb1);
    __syncthreads();

    const int NT = KPAD / 16;   // 19
    for (int kt = 0; kt < NT; kt++) {
        const int cur = kt & 1;
        if (kt + 1 < NT) {
            int base = (kt + 1) * 16 + lk;
            bool v1 = (base + 7 < EMB);
            ra0 = *(const float4*)(asrc + base);
            ra1 = v1 ? *(const float4*)(asrc + base + 4) : z4;
            rb0 = bvalid ? *(const float4*)(wsrc + base) : z4;
            rb1 = (bvalid && v1) ? *(const float4*)(wsrc + base + 4) : z4;
        }

        const __half* Ab = hb + cur * 6144;
        const __half* Bb = Ab + 3072;
        uint4 af[4];
#pragma unroll
        for (int mt = 0; mt < 4; mt++) {
            int r = wm * 64 + mt * 16 + gID;
            af[mt].x = *(const unsigned*)&Ab[r * 24 + tig * 2];
            af[mt].y = *(const unsigned*)&Ab[(r + 8) * 24 + tig * 2];
            af[mt].z = *(const unsigned*)&Ab[r * 24 + tig * 2 + 8];
            af[mt].w = *(const unsigned*)&Ab[(r + 8) * 24 + tig * 2 + 8];
        }
#pragma unroll
        for (int nt = 0; nt < 4; nt++) {
            int n = wn * 32 + nt * 8 + gID;
            uint2 bf;
            bf.x = *(const unsigned*)&Bb[n * 24 + tig * 2];
            bf.y = *(const unsigned*)&Bb[n * 24 + tig * 2 + 8];
#pragma unroll
            for (int mt = 0; mt < 4; mt++)
                mma_f16(acc[mt][nt], af[mt], bf);
        }

        if (kt + 1 < NT) {
            __half* An = hb + (cur ^ 1) * 6144;
            *(uint4*)&An[lrow * 24 + lk]        = pack8h(ra0, ra1);
            *(uint4*)&An[3072 + lrow * 24 + lk] = pack8h(rb0, rb1);
            __syncthreads();
        }
    }
    __syncthreads();

    float* sm_e = smraw;   // [128][33]
    const int bt = bm >> 5;
#pragma unroll
    for (int ch = 0; ch < 4; ch++) {
        if (wn == ch) {
#pragma unroll
            for (int mt = 0; mt < 4; mt++) {
                int row = wm * 64 + mt * 16 + gID;
#pragma unroll
                for (int nt = 0; nt < 4; nt++) {
                    int col = nt * 8 + tig * 2;
                    sm_e[row * 33 + col]           = acc[mt][nt][0];
                    sm_e[row * 33 + col + 1]       = acc[mt][nt][1];
                    sm_e[(row + 8) * 33 + col]     = acc[mt][nt][2];
                    sm_e[(row + 8) * 33 + col + 1] = acc[mt][nt][3];
                }
            }
        }
        __syncthreads();
#pragma unroll 4
        for (int task = wid; task < 128; task += 8) {
            int np = task >> 2, tt = task & 3;
            int n = bn + ch * 32 + np;
            if (n < GH) {
                float bias = b_ih[n] + b_hh[n];
                g_xg16[((size_t)(bt + tt) * GH + n) * 32 + lane] =
                    __float2half(sm_e[(tt * 32 + lane) * 33 + np] + bias);
            }
        }
        __syncthreads();
    }
}

// ===========================================================================
// Kernel 2: persistent fp16 tensor-core LSTM scan.
// Per-warp producer wait: warp wid needs only blocks [wid*16, wid*16+16).
// release/acquire flags, no threadfence.
// ===========================================================================
__global__ void __launch_bounds__(256, 1)
lstm_persist_mma(const float* __restrict__ Whh)
{
    extern __shared__ float sm[];
    unsigned* w_fs = (unsigned*)sm;   // 16128 words: [kt][nt][lane][word]
    float* red = sm + 16128;          // 8704 floats: [ks(8)][b(32)][34]

    const int tid  = threadIdx.x;
    const int bid  = blockIdx.x;
    const int j0   = bid * JB;
    const int wid  = tid >> 5;
    const int lane = tid & 31;
    const int g    = lane >> 2;
    const int tig  = lane & 3;

    const int cb  = tid & 31;
    const int cjj = tid >> 5;
    const int j   = j0 + cjj;

    // h A-fragment (fp16) write index for (row=cb, k=j)
    const int kk2   = j >> 4;
    const int kp2   = j & 15;
    const int khi   = kp2 >> 3;
    const int pp    = kp2 & 1;
    const int tig2  = (kp2 >> 1) & 3;
    const int gID2  = cb & 7;
    const int rhi   = (cb >> 3) & 1;
    const int mt2   = cb >> 4;
    const int lane2 = gID2 * 4 + tig2;
    const int fidx16 = (((kk2 * 2 + mt2) * 32 + lane2) * 4 + (khi * 2 + rhi)) * 2 + pp;

    // producers for this warp's k-slice
    const int pbase = wid * 16;
    const int pcnt  = (wid < 7) ? 16 : 13;

    // ---- pack W slice into fp16 B-fragment order, once ----
    for (int idx = tid; idx < NKT * 256; idx += 256) {
        int wrd = idx & 1;
        int ln  = (idx >> 1) & 31;
        int nt  = (idx >> 6) & 3;
        int kt  = idx >> 8;
        int k0e = kt * 16 + (ln & 3) * 2 + wrd * 8;
        int rw  = nt * HID + j0 + (ln >> 2);
        float v0 = (k0e     < HID) ? Whh[(size_t)rw * HID + k0e]     : 0.f;
        float v1 = (k0e + 1 < HID) ? Whh[(size_t)rw * HID + k0e + 1] : 0.f;
        ((__half2*)w_fs)[idx] = __floats2half2_rn(v0, v1);
    }

    const int kb = wid * 8;   // warp 7: 7 tiles (guarded)

    float c_reg = 0.f;
    float gate[4];
#pragma unroll
    for (int gg = 0; gg < 4; gg++)
        gate[gg] = __half2float(g_xg16[((size_t)(gg * HID + j)) * BATCH + cb]);
    __syncthreads();

    for (int t = 0; t < SEQ; t++) {
        if (t > 0) {
            // ---- per-warp acquire wait on this warp's 16 producers ----
            const unsigned want = (unsigned)t;
            if (lane < pcnt) {
                const unsigned* fp = &g_slot[(pbase + lane) * 32];
                while (flag_acquire(fp) != want) { }
            }
            __syncwarp();

            float c[2][4][4];
#pragma unroll
            for (int mt = 0; mt < 2; mt++)
#pragma unroll
                for (int nt = 0; nt < 4; nt++)
#pragma unroll
                    for (int rr = 0; rr < 4; rr++) c[mt][nt][rr] = 0.f;

            const uint4* hf = (const uint4*)(g_hfrag16 + (size_t)(t - 1) * FRAG16_PER_T);

            uint4 a[8][2];
#pragma unroll
            for (int i = 0; i < 8; i++) {
                int kk = kb + i;
                if (kk < NKT) {
                    a[i][0] = hf[(kk * 2 + 0) * 32 + lane];
                    a[i][1] = hf[(kk * 2 + 1) * 32 + lane];
                }
            }
            const uint2* wv = (const uint2*)w_fs;
#pragma unroll
            for (int i = 0; i < 8; i++) {
                int kk = kb + i;
                if (kk < NKT) {
                    uint2 bfr[4];
#pragma unroll
                    for (int nt = 0; nt < 4; nt++)
                        bfr[nt] = wv[(kk * 4 + nt) * 32 + lane];
#pragma unroll
                    for (int nt = 0; nt < 4; nt++) {
                        mma_f16(c[0][nt], a[i][0], bfr[nt]);
                        mma_f16(c[1][nt], a[i][1], bfr[nt]);
                    }
                }
            }

            float* myred = red + wid * 1088;
#pragma unroll
            for (int mt = 0; mt < 2; mt++) {
                const int b0 = mt * 16 + g;
#pragma unroll
                for (int nt = 0; nt < 4; nt++) {
                    const int col = nt * 8 + 2 * tig;
                    *(float2*)&myred[b0 * 34 + col]       = make_float2(c[mt][nt][0], c[mt][nt][1]);
                    *(float2*)&myred[(b0 + 8) * 34 + col] = make_float2(c[mt][nt][2], c[mt][nt][3]);
                }
            }
            __syncthreads();

#pragma unroll
            for (int gg = 0; gg < 4; gg++) {
                float s = 0.f;
#pragma unroll
                for (int ks = 0; ks < 8; ks++)
                    s += red[ks * 1088 + cb * 34 + gg * 8 + cjj];
                gate[gg] += s;
            }
        }

        // ---- activations + state update ----
        {
            float iv = fast_sig(gate[0]);
            float fv = fast_sig(gate[1]);
            float gv = fast_tanh(gate[2]);
            float ov = fast_sig(gate[3]);
            c_reg = fv * c_reg + iv * gv;
            float hn = ov * fast_tanh(c_reg);
            __half h16 = __float2half(hn);
            g_hfrag16[(size_t)t * FRAG16_PER_T + fidx16] = h16;
            g_hs16[((size_t)t * HID + j) * BATCH + cb] = h16;
        }

        __syncthreads();    // h stores issued block-wide; also protects red reuse

        if (t < SEQ - 1) {
            if (tid == 0)
                flag_release(&g_slot[bid * 32], (unsigned)(t + 1));
            // prefetch next-step gates (in flight during next poll)
            const __half* xgt = g_xg16 + (size_t)(t + 1) * GH * BATCH;
#pragma unroll
            for (int gg = 0; gg < 4; gg++)
                gate[gg] = __half2float(xgt[((size_t)(gg * HID + j)) * BATCH + cb]);
        }
    }
}

// ===========================================================================
// Kernel 3: fused tag projection + log_softmax(axis=batch).
// ===========================================================================
__global__ void __launch_bounds__(288)
tag_lsm_kernel(const float* __restrict__ lin_w,
               const float* __restrict__ lin_b)
{
    __shared__ float w_sm[TAGS * HID];
    __shared__ float part[8 * 32 * 10];

    const int t    = blockIdx.x;
    const int tid  = threadIdx.x;
    const int w    = tid >> 5;
    const int lane = tid & 31;

    for (int i = tid; i < TAGS * HID; i += 288) w_sm[i] = lin_w[i];
    __syncthreads();

    if (w < 8) {
        float acc[TAGS];
#pragma unroll
        for (int k = 0; k < TAGS; k++) acc[k] = 0.f;
        const __half* h = g_hs16 + (size_t)t * HID * BATCH;
        const int jbase = w * 128;
        const int jcnt  = (w < 7) ? 128 : 104;
#pragma unroll 2
        for (int jj = 0; jj < jcnt; jj += 4) {
            const int j4 = jbase + jj;
            float hv0 = __half2float(h[(j4 + 0) * 32 + lane]);
            float hv1 = __half2float(h[(j4 + 1) * 32 + lane]);
            float hv2 = __half2float(h[(j4 + 2) * 32 + lane]);
            float hv3 = __half2float(h[(j4 + 3) * 32 + lane]);
#pragma unroll
            for (int k = 0; k < TAGS; k++) {
                float4 wv = *(const float4*)&w_sm[k * HID + j4];
                acc[k] += hv0 * wv.x + hv1 * wv.y + hv2 * wv.z + hv3 * wv.w;
            }
        }
#pragma unroll
        for (int k = 0; k < TAGS; k++)
            part[(w * 32 + lane) * 10 + k] = acc[k];
    }
    __syncthreads();

    {
        const int k = w;
        const int b = lane;
        float v = lin_b[k];
#pragma unroll
        for (int ww = 0; ww < 8; ww++) v += part[(ww * 32 + b) * 10 + k];
        float m = v;
#pragma unroll
        for (int off = 16; off; off >>= 1) m = fmaxf(m, __shfl_xor_sync(0xffffffffu, m, off));
        float e = __expf(v - m);
        float s = e;
#pragma unroll
        for (int off = 16; off; off >>= 1) s += __shfl_xor_sync(0xffffffffu, s, off);
        g_tag[(t * BATCH + b) * TAGS + k] = v - m - __logf(s);
    }
}

// ===========================================================================
// Kernel 4: CRF via warp shuffles — no __syncthreads in the recursion.
// 512 threads, 16 warps; warp w handles batches 2w, 2w+1 (lanes 0-8 / 16-24).
// ===========================================================================
__global__ void __launch_bounds__(512)
crf_kernel(const int* __restrict__ y,
           const float* __restrict__ start_t,
           const float* __restrict__ end_t,
           const float* __restrict__ trans,
           float* __restrict__ out)
{
    __shared__ float tr[TAGS][TAGS];
    __shared__ float st[TAGS], en[TAGS];
    __shared__ float numer_part[BATCH][17];
    __shared__ float res[BATCH];

    const int tid = threadIdx.x;
    if (tid < 81) tr[tid / 9][tid % 9] = trans[tid];
    if (tid < 9) { st[tid] = start_t[tid]; en[tid] = end_t[tid]; }
    __syncthreads();

    // ---- numerator: b = tid>>4, chunk c = tid&15 (13 t's each) ----
    {
        const int b = tid >> 4, c = tid & 15;
        int lo = c * 13, hi = min(SEQ, lo + 13);
        float s = 0.f;
        int yprev;
        if (c == 0) {
            int y0 = y[b];
            s = st[y0] + g_tag[b * TAGS + y0];
            yprev = y0;
            lo = 1;
        } else {
            yprev = y[(lo - 1) * BATCH + b];
        }
        for (int t = lo; t < hi; t++) {
            int yt = y[t * BATCH + b];
            s += tr[yprev][yt] + g_tag[(t * BATCH + b) * TAGS + yt];
            yprev = yt;
        }
        if (hi == SEQ) s += en[yprev];
        numer_part[b][c] = s;
    }

    // ---- alpha recursion in registers ----
    const int w    = tid >> 5;
    const int lane = tid & 31;
    const int half = lane & 16;          // 0 or 16
    const int k    = lane & 15;          // tag index (active if < 9)
    const int b2   = w * 2 + (lane >> 4);
    const int kc   = (k < 9) ? k : 0;

    float trc[9];
#pragma unroll
    for (int kp = 0; kp < 9; kp++) trc[kp] = tr[kp][kc];

    float a = st[kc] + g_tag[b2 * TAGS + kc];
    float em_next = g_tag[(1 * BATCH + b2) * TAGS + kc];

    for (int t = 1; t < SEQ; t++) {
        float em_cur = em_next;
        if (t + 1 < SEQ)
            em_next = g_tag[((t + 1) * BATCH + b2) * TAGS + kc];

        float v[9];
#pragma unroll
        for (int kp = 0; kp < 9; kp++)
            v[kp] = __shfl_sync(0xffffffffu, a, half + kp) + trc[kp];
        float m01 = fmaxf(v[0], v[1]), m23 = fmaxf(v[2], v[3]);
        float m45 = fmaxf(v[4], v[5]), m67 = fmaxf(v[6], v[7]);
        float m = fmaxf(fmaxf(fmaxf(m01, m23), fmaxf(m45, m67)), v[8]);
        float s = 0.f;
#pragma unroll
        for (int kp = 0; kp < 9; kp++) s += __expf(v[kp] - m);
        a = m + __logf(s) + em_cur;
    }

    // ---- logz per batch: gather a+en over the 9 lanes ----
    {
        float fa = a + en[kc];
        float v[9];
#pragma unroll
        for (int kp = 0; kp < 9; kp++)
            v[kp] = __shfl_sync(0xffffffffu, fa, half + kp);
        float m01 = fmaxf(v[0], v[1]), m23 = fmaxf(v[2], v[3]);
        float m45 = fmaxf(v[4], v[5]), m67 = fmaxf(v[6], v[7]);
        float m = fmaxf(fmaxf(fmaxf(m01, m23), fmaxf(m45, m67)), v[8]);
        float s = 0.f;
#pragma unroll
        for (int kp = 0; kp < 9; kp++) s += __expf(v[kp] - m);
        if (k == 0) res[b2] = -(m + __logf(s));
    }
    __syncthreads();

    // ---- final: numerator sums + logz, reduce 32 batches ----
    if (tid < 32) {
        float s = res[tid];
#pragma unroll
        for (int c = 0; c < 16; c++) s += numer_part[tid][c];
#pragma unroll
        for (int off = 16; off; off >>= 1) s += __shfl_down_sync(0xffffffffu, s, off);
        if (tid == 0) out[0] = s;
    }
}

// ===========================================================================
// launch
// ===========================================================================
extern "C" void kernel_launch(void* const* d_in, const int* in_sizes, int n_in,
                              void* d_out, int out_size)
{
    const int*   x       = (const int*)  d_in[0];
    const int*   y       = (const int*)  d_in[1];
    const float* embed_w = (const float*)d_in[2];
    const float* W_ih    = (const float*)d_in[3];
    const float* W_hh    = (const float*)d_in[4];
    const float* b_ih    = (const float*)d_in[5];
    const float* b_hh    = (const float*)d_in[6];
    const float* lin_w   = (const float*)d_in[7];
    const float* lin_b   = (const float*)d_in[8];
    const float* start_t = (const float*)d_in[9];
    const float* end_t   = (const float*)d_in[10];
    const float* trans   = (const float*)d_in[11];
    float* out = (float*)d_out;

    const int smem_bytes = 16128 * 4 + 8704 * 4;   // 99328
    cudaFuncSetAttribute(lstm_persist_mma,
                         cudaFuncAttributeMaxDynamicSharedMemorySize, smem_bytes);

    xg_fused_kernel<<<dim3(32, 50), 256>>>(x, embed_w, W_ih, b_ih, b_hh);

    lstm_persist_mma<<<NBLK, 256, smem_bytes>>>(W_hh);

    tag_lsm_kernel<<<SEQ, 288>>>(lin_w, lin_b);
    crf_kernel<<<1, 512>>>(y, start_t, end_t, trans, out);
}